// round 6
// baseline (speedup 1.0000x reference)
#include <cuda_runtime.h>
#include <cuda_bf16.h>
#include <cuda_fp16.h>

#define S_LEN   2048
#define DMODEL  1024
#define NHEAD   16
#define HDIM    64
#define BATCH   2
#define M_ROWS  (BATCH * S_LEN)   /* 4096 */

// Scratch (allocation-free rule: __device__ globals).
__device__ float g_Q[BATCH * NHEAD * S_LEN * HDIM];
__device__ float g_K[BATCH * NHEAD * S_LEN * HDIM];
__device__ float g_V[BATCH * NHEAD * S_LEN * HDIM];
__device__ float g_attn[BATCH * S_LEN * DMODEL];

// ---------------------------------------------------------------------------
// helpers
// ---------------------------------------------------------------------------
// D += A * B  (m16n8k16, bf16 inputs, f32 accumulate)
__device__ __forceinline__ void mma16bf(float* d, const unsigned* a, const unsigned* b) {
    asm volatile(
        "mma.sync.aligned.m16n8k16.row.col.f32.bf16.bf16.f32 "
        "{%0,%1,%2,%3}, {%4,%5,%6,%7}, {%8,%9}, {%0,%1,%2,%3};\n"
        : "+f"(d[0]), "+f"(d[1]), "+f"(d[2]), "+f"(d[3])
        : "r"(a[0]), "r"(a[1]), "r"(a[2]), "r"(a[3]), "r"(b[0]), "r"(b[1]));
}

// D += A * B  (m16n8k16, fp16 inputs, f32 accumulate)
__device__ __forceinline__ void mma16h(float* d, const unsigned* a, const unsigned* b) {
    asm volatile(
        "mma.sync.aligned.m16n8k16.row.col.f32.f16.f16.f32 "
        "{%0,%1,%2,%3}, {%4,%5,%6,%7}, {%8,%9}, {%0,%1,%2,%3};\n"
        : "+f"(d[0]), "+f"(d[1]), "+f"(d[2]), "+f"(d[3])
        : "r"(a[0]), "r"(a[1]), "r"(a[2]), "r"(a[3]), "r"(b[0]), "r"(b[1]));
}

// ldmatrix x4 (non-transposed)
__device__ __forceinline__ void ldsm4(unsigned* r, unsigned addr) {
    asm volatile(
        "ldmatrix.sync.aligned.m8n8.x4.shared.b16 {%0,%1,%2,%3}, [%4];"
        : "=r"(r[0]), "=r"(r[1]), "=r"(r[2]), "=r"(r[3]) : "r"(addr));
}

__device__ __forceinline__ unsigned bfpack(float lo_k, float hi_k) {
    __nv_bfloat162 t = __floats2bfloat162_rn(lo_k, hi_k);  // .x = even k (low)
    return *(unsigned*)&t;
}

__device__ __forceinline__ unsigned hpack(float lo_k, float hi_k) {
    __half2 t = __floats2half2_rn(lo_k, hi_k);             // .x = even k (low)
    return *(unsigned*)&t;
}

__device__ __forceinline__ unsigned smem_u32(const void* p) {
    return (unsigned)__cvta_generic_to_shared(p);
}

// ---------------------------------------------------------------------------
// 3xbf16-split GEMM + bias:  C[m,n] = sum_k A[m,k] * W[n,k] + bias[n]
// CTA tile 128x128, BK=16, 256 threads (8 warps, 2Mx4N, warp tile 64x32).
// x = hi + lo (both bf16); hi*hi + hi*lo + lo*hi (drop lo*lo ~2^-18).
// Fragment loads via ldmatrix.x4 (12 per iter vs 48 LDS.32).
// headsplit=1: write C to [B,H,S,64]; else flat [m,1024].
// ---------------------------------------------------------------------------
#define GW 12   /* smem row stride in 32-bit words (8 words data + 4 pad) */

__global__ __launch_bounds__(256) void gemm_bf16_kernel(
    const float* __restrict__ A, const float* __restrict__ W,
    const float* __restrict__ bias, float* __restrict__ C, int headsplit)
{
    __shared__ unsigned Ah[128 * GW], Al[128 * GW];
    __shared__ unsigned Bh[128 * GW], Bl[128 * GW];

    const int tid  = threadIdx.x;
    const int lane = tid & 31;
    const int wid  = tid >> 5;
    const int wm   = wid >> 2;        // 0..1  -> 64 rows
    const int wn   = wid & 3;         // 0..3  -> 32 cols
    const int g    = lane >> 2;       // 0..7
    const int c    = lane & 3;        // 0..3
    const int bm   = blockIdx.x;
    const int bn   = blockIdx.y;

    const int lrow = tid >> 1;        // 0..127
    const int lk   = (tid & 1) << 3;  // float-k offset: 0 or 8
    const int wbase = lrow * GW + (lk >> 1);  // word offset: 0 or 4

    // ldmatrix per-lane byte offsets
    // A matrices: 0:(m0-7,klo) 1:(m8-15,klo) 2:(m0-7,khi) 3:(m8-15,khi)
    const unsigned a_off =
        ((unsigned)((wm * 64 + ((lane >> 3) & 1) * 8 + (lane & 7)) * GW
                    + (lane >> 4) * 4)) * 4u;
    // B matrices: 0:(n_lo,klo) 1:(n_lo,khi) 2:(n_hi,klo) 3:(n_hi,khi)
    const unsigned b_off =
        ((unsigned)((wn * 32 + (lane >> 4) * 8 + (lane & 7)) * GW
                    + ((lane >> 3) & 1) * 4)) * 4u;

    const unsigned ah_b = smem_u32(Ah), al_b = smem_u32(Al);
    const unsigned bh_b = smem_u32(Bh), bl_b = smem_u32(Bl);

    const float* Ap = A + (size_t)(bm * 128 + lrow) * DMODEL + lk;
    const float* Wp = W + (size_t)(bn * 128 + lrow) * DMODEL + lk;

    float acc[4][4][4];
#pragma unroll
    for (int i = 0; i < 4; i++)
#pragma unroll
        for (int j = 0; j < 4; j++)
#pragma unroll
            for (int k = 0; k < 4; k++) acc[i][j][k] = 0.f;

    float4 rA0 = *(const float4*)(Ap);
    float4 rA1 = *(const float4*)(Ap + 4);
    float4 rW0 = *(const float4*)(Wp);
    float4 rW1 = *(const float4*)(Wp + 4);

    for (int k0 = 0; k0 < DMODEL; k0 += 16) {
        float va[8] = {rA0.x, rA0.y, rA0.z, rA0.w, rA1.x, rA1.y, rA1.z, rA1.w};
        float vw[8] = {rW0.x, rW0.y, rW0.z, rW0.w, rW1.x, rW1.y, rW1.z, rW1.w};
        float hafl[8], hwfl[8];
        unsigned ha[4], la[4], hw[4], lw[4];
#pragma unroll
        for (int i = 0; i < 8; i++) {
            hafl[i] = __bfloat162float(__float2bfloat16_rn(va[i]));
            hwfl[i] = __bfloat162float(__float2bfloat16_rn(vw[i]));
        }
#pragma unroll
        for (int i = 0; i < 4; i++) {
            ha[i] = bfpack(hafl[2*i], hafl[2*i+1]);
            la[i] = bfpack(va[2*i] - hafl[2*i], va[2*i+1] - hafl[2*i+1]);
            hw[i] = bfpack(hwfl[2*i], hwfl[2*i+1]);
            lw[i] = bfpack(vw[2*i] - hwfl[2*i], vw[2*i+1] - hwfl[2*i+1]);
        }

        __syncthreads();
        *(uint4*)&Ah[wbase] = make_uint4(ha[0], ha[1], ha[2], ha[3]);
        *(uint4*)&Al[wbase] = make_uint4(la[0], la[1], la[2], la[3]);
        *(uint4*)&Bh[wbase] = make_uint4(hw[0], hw[1], hw[2], hw[3]);
        *(uint4*)&Bl[wbase] = make_uint4(lw[0], lw[1], lw[2], lw[3]);
        __syncthreads();

        if (k0 + 16 < DMODEL) {
            rA0 = *(const float4*)(Ap + k0 + 16);
            rA1 = *(const float4*)(Ap + k0 + 20);
            rW0 = *(const float4*)(Wp + k0 + 16);
            rW1 = *(const float4*)(Wp + k0 + 20);
        }

        unsigned ah[4][4], al[4][4], bhf[2][4], blf[2][4];
#pragma unroll
        for (int ma = 0; ma < 4; ma++) {
            const unsigned moff = (unsigned)(ma * 16 * GW) * 4u;
            ldsm4(ah[ma], ah_b + a_off + moff);
            ldsm4(al[ma], al_b + a_off + moff);
        }
#pragma unroll
        for (int p = 0; p < 2; p++) {
            const unsigned noff = (unsigned)(p * 16 * GW) * 4u;
            ldsm4(bhf[p], bh_b + b_off + noff);
            ldsm4(blf[p], bl_b + b_off + noff);
        }
#pragma unroll
        for (int ma = 0; ma < 4; ma++)
#pragma unroll
            for (int na = 0; na < 4; na++) {
                const unsigned* bhp = &bhf[na >> 1][(na & 1) * 2];
                const unsigned* blp = &blf[na >> 1][(na & 1) * 2];
                mma16bf(acc[ma][na], ah[ma], blp);
                mma16bf(acc[ma][na], al[ma], bhp);
                mma16bf(acc[ma][na], ah[ma], bhp);
            }
    }

    // epilogue
#pragma unroll
    for (int ma = 0; ma < 4; ma++) {
        const int m0 = bm * 128 + wm * 64 + ma * 16 + g;
#pragma unroll
        for (int na = 0; na < 4; na++) {
            const int n  = bn * 128 + wn * 32 + na * 8 + (c << 1);
            const float b0 = bias[n], b1 = bias[n + 1];
            float2 v0 = make_float2(acc[ma][na][0] + b0, acc[ma][na][1] + b1);
            float2 v1 = make_float2(acc[ma][na][2] + b0, acc[ma][na][3] + b1);
            if (headsplit) {
                const int h = n >> 6, d = n & 63;
                const int b_0 = m0 >> 11, s_0 = m0 & (S_LEN - 1);
                const int b_1 = (m0 + 8) >> 11, s_1 = (m0 + 8) & (S_LEN - 1);
                *(float2*)&C[((size_t)((b_0 * NHEAD + h) * S_LEN + s_0)) * HDIM + d] = v0;
                *(float2*)&C[((size_t)((b_1 * NHEAD + h) * S_LEN + s_1)) * HDIM + d] = v1;
            } else {
                *(float2*)&C[(size_t)m0 * DMODEL + n]       = v0;
                *(float2*)&C[(size_t)(m0 + 8) * DMODEL + n] = v1;
            }
        }
    }
}

// ---------------------------------------------------------------------------
// Flash attention, fp16 MMA (same 10-bit mantissa as tf32) + ldmatrix.
// grid = (32 qtiles of 64 rows, B*H=32). 128 threads = 4 warps x 16 rows.
// Ks: [key][d-pair words]   (64 x 36 words, SW-free via stride padding)
// Vs: [d][key-pair words]   (transpose-packed at load via register pairing)
// Ps: [qrow][key-pair words]
// ---------------------------------------------------------------------------
#define KW 36   /* word stride: 32 data + 4 pad */

__global__ __launch_bounds__(128) void attn_fp16_kernel(
    const float* __restrict__ Q, const float* __restrict__ K,
    const float* __restrict__ V, float* __restrict__ Out)
{
    __shared__ unsigned Ks[64 * KW];
    __shared__ unsigned Vs[64 * KW];
    __shared__ unsigned Ps[64 * KW];

    const int tid  = threadIdx.x;
    const int lane = tid & 31;
    const int w    = tid >> 5;
    const int g    = lane >> 2;
    const int c    = lane & 3;
    const int qtile = blockIdx.x;
    const int bh    = blockIdx.y;

    const unsigned ks_b = smem_u32(Ks), vs_b = smem_u32(Vs), ps_b = smem_u32(Ps);
    // B-operand ldmatrix lane offset (matrices: n_lo/klo, n_lo/khi, n_hi/klo, n_hi/khi)
    const unsigned off_b =
        ((unsigned)(((lane >> 4) * 8 + (lane & 7)) * KW + ((lane >> 3) & 1) * 4)) * 4u;
    // A-operand (P) ldmatrix lane offset (matrices: m_lo/klo, m_hi/klo, m_lo/khi, m_hi/khi)
    const unsigned off_a =
        ((unsigned)((w * 16 + ((lane >> 3) & 1) * 8 + (lane & 7)) * KW
                    + (lane >> 4) * 4)) * 4u;

    // Q fragments (fp16, pre-scaled by 1/8)
    const float* Qb = Q + ((size_t)bh * S_LEN + qtile * 64 + w * 16) * HDIM;
    unsigned qa[4][4];
#pragma unroll
    for (int ks = 0; ks < 4; ks++) {
        const int d0 = ks * 16 + 2 * c;
        qa[ks][0] = hpack(0.125f * Qb[(size_t)g * HDIM + d0],
                          0.125f * Qb[(size_t)g * HDIM + d0 + 1]);
        qa[ks][1] = hpack(0.125f * Qb[(size_t)(g + 8) * HDIM + d0],
                          0.125f * Qb[(size_t)(g + 8) * HDIM + d0 + 1]);
        qa[ks][2] = hpack(0.125f * Qb[(size_t)g * HDIM + d0 + 8],
                          0.125f * Qb[(size_t)g * HDIM + d0 + 9]);
        qa[ks][3] = hpack(0.125f * Qb[(size_t)(g + 8) * HDIM + d0 + 8],
                          0.125f * Qb[(size_t)(g + 8) * HDIM + d0 + 9]);
    }

    float oacc[8][4];
#pragma unroll
    for (int i = 0; i < 8; i++)
#pragma unroll
        for (int j = 0; j < 4; j++) oacc[i][j] = 0.f;
    float m0 = -1e30f, m1 = -1e30f, l0 = 0.f, l1 = 0.f;

    const float* Kb = K + (size_t)bh * S_LEN * HDIM;
    const float* Vb = V + (size_t)bh * S_LEN * HDIM;

    for (int kt = 0; kt < S_LEN / 64; kt++) {
        // ---- K tile: [key][d] -> fp16 d-pairs, row=key ----
        const float4* ksrc = (const float4*)(Kb + (size_t)kt * 64 * HDIM);
#pragma unroll
        for (int i = 0; i < 8; i++) {
            const int f   = tid + i * 128;
            const int row = f >> 4;
            const int wcol = (f & 15) * 2;
            float4 kv = ksrc[f];
            *(uint2*)&Ks[row * KW + wcol] =
                make_uint2(hpack(kv.x, kv.y), hpack(kv.z, kv.w));
        }
        // ---- V tile: transpose-pack -> row=d, words=key-pairs ----
        const float4* vsrc = (const float4*)(Vb + (size_t)kt * 64 * HDIM);
#pragma unroll
        for (int i = 0; i < 4; i++) {
            const int kp = lane;               // key pair 0..31
            const int dg = (tid >> 5) + i * 4; // d group of 4: 0..15
            float4 v0 = vsrc[(2 * kp) * 16 + dg];
            float4 v1 = vsrc[(2 * kp + 1) * 16 + dg];
            Vs[(dg * 4 + 0) * KW + kp] = hpack(v0.x, v1.x);
            Vs[(dg * 4 + 1) * KW + kp] = hpack(v0.y, v1.y);
            Vs[(dg * 4 + 2) * KW + kp] = hpack(v0.z, v1.z);
            Vs[(dg * 4 + 3) * KW + kp] = hpack(v0.w, v1.w);
        }
        __syncthreads();

        // ---- S = (Q/8) @ K^T ----
        float sacc[8][4];
#pragma unroll
        for (int i = 0; i < 8; i++)
#pragma unroll
            for (int j = 0; j < 4; j++) sacc[i][j] = 0.f;
#pragma unroll
        for (int ks = 0; ks < 4; ks++) {
#pragma unroll
            for (int p = 0; p < 4; p++) {
                unsigned kb[4];
                ldsm4(kb, ks_b + (unsigned)(p * 16 * KW + ks * 8) * 4u + off_b);
                mma16h(sacc[2 * p],     qa[ks], kb);
                mma16h(sacc[2 * p + 1], qa[ks], kb + 2);
            }
        }

        // ---- online softmax ----
        float tm0 = -1e30f, tm1 = -1e30f;
#pragma unroll
        for (int na = 0; na < 8; na++) {
            tm0 = fmaxf(tm0, fmaxf(sacc[na][0], sacc[na][1]));
            tm1 = fmaxf(tm1, fmaxf(sacc[na][2], sacc[na][3]));
        }
        tm0 = fmaxf(tm0, __shfl_xor_sync(0xffffffffu, tm0, 1));
        tm0 = fmaxf(tm0, __shfl_xor_sync(0xffffffffu, tm0, 2));
        tm1 = fmaxf(tm1, __shfl_xor_sync(0xffffffffu, tm1, 1));
        tm1 = fmaxf(tm1, __shfl_xor_sync(0xffffffffu, tm1, 2));
        const float mn0 = fmaxf(m0, tm0);
        const float mn1 = fmaxf(m1, tm1);
        const float alpha0 = __expf(m0 - mn0);
        const float alpha1 = __expf(m1 - mn1);
        m0 = mn0; m1 = mn1;

        float rs0 = 0.f, rs1 = 0.f;
        const int pr0 = (w * 16 + g) * KW;
        const int pr1 = (w * 16 + g + 8) * KW;
#pragma unroll
        for (int na = 0; na < 8; na++) {
            const float p0 = __expf(sacc[na][0] - mn0);
            const float p1 = __expf(sacc[na][1] - mn0);
            const float p2 = __expf(sacc[na][2] - mn1);
            const float p3 = __expf(sacc[na][3] - mn1);
            rs0 += p0 + p1;
            rs1 += p2 + p3;
            Ps[pr0 + na * 4 + c] = hpack(p0, p1);
            Ps[pr1 + na * 4 + c] = hpack(p2, p3);
        }
        rs0 += __shfl_xor_sync(0xffffffffu, rs0, 1);
        rs0 += __shfl_xor_sync(0xffffffffu, rs0, 2);
        rs1 += __shfl_xor_sync(0xffffffffu, rs1, 1);
        rs1 += __shfl_xor_sync(0xffffffffu, rs1, 2);
        l0 = l0 * alpha0 + rs0;
        l1 = l1 * alpha1 + rs1;
#pragma unroll
        for (int na = 0; na < 8; na++) {
            oacc[na][0] *= alpha0; oacc[na][1] *= alpha0;
            oacc[na][2] *= alpha1; oacc[na][3] *= alpha1;
        }
        __syncwarp();   // Ps written and read by this warp only

        // ---- O += P @ V ----
#pragma unroll
        for (int ks = 0; ks < 4; ks++) {
            unsigned pa[4];
            ldsm4(pa, ps_b + (unsigned)(ks * 8) * 4u + off_a);
#pragma unroll
            for (int p = 0; p < 4; p++) {
                unsigned vb[4];
                ldsm4(vb, vs_b + (unsigned)(p * 16 * KW + ks * 8) * 4u + off_b);
                mma16h(oacc[2 * p],     pa, vb);
                mma16h(oacc[2 * p + 1], pa, vb + 2);
            }
        }
        __syncthreads();   // all reads done before next tile's stores
    }

    // ---- epilogue ----
    const float inv0 = 1.f / l0;
    const float inv1 = 1.f / l1;
    const int b = bh >> 4, h = bh & 15;
    const int s0 = qtile * 64 + w * 16 + g;
    float* o0 = Out + ((size_t)(b * S_LEN + s0)) * DMODEL + h * HDIM;
    float* o1 = o0 + (size_t)8 * DMODEL;
#pragma unroll
    for (int na = 0; na < 8; na++) {
        const int col = na * 8 + (c << 1);
        *(float2*)(o0 + col) = make_float2(oacc[na][0] * inv0, oacc[na][1] * inv0);
        *(float2*)(o1 + col) = make_float2(oacc[na][2] * inv1, oacc[na][3] * inv1);
    }
}

// ---------------------------------------------------------------------------
extern "C" void kernel_launch(void* const* d_in, const int* in_sizes, int n_in,
                              void* d_out, int out_size)
{
    const float* query = (const float*)d_in[0];
    const float* key   = (const float*)d_in[1];
    const float* value = (const float*)d_in[2];
    const float* Wq = (const float*)d_in[3];
    const float* bq = (const float*)d_in[4];
    const float* Wk = (const float*)d_in[5];
    const float* bk = (const float*)d_in[6];
    const float* Wv = (const float*)d_in[7];
    const float* bv = (const float*)d_in[8];
    const float* Wo = (const float*)d_in[9];
    const float* bo = (const float*)d_in[10];
    float* out = (float*)d_out;

    float *pQ, *pK, *pV, *pA;
    cudaGetSymbolAddress((void**)&pQ, g_Q);
    cudaGetSymbolAddress((void**)&pK, g_K);
    cudaGetSymbolAddress((void**)&pV, g_V);
    cudaGetSymbolAddress((void**)&pA, g_attn);

    dim3 ggrid(M_ROWS / 128, DMODEL / 128);
    gemm_bf16_kernel<<<ggrid, 256>>>(query, Wq, bq, pQ, 1);
    gemm_bf16_kernel<<<ggrid, 256>>>(key,   Wk, bk, pK, 1);
    gemm_bf16_kernel<<<ggrid, 256>>>(value, Wv, bv, pV, 1);

    dim3 agrid(S_LEN / 64, BATCH * NHEAD);
    attn_fp16_kernel<<<agrid, 128>>>(pQ, pK, pV, pA);

    gemm_bf16_kernel<<<ggrid, 256>>>(pA, Wo, bo, out, 0);
}

// round 7
// speedup vs baseline: 1.1415x; 1.1415x over previous
#include <cuda_runtime.h>
#include <cuda_bf16.h>
#include <cuda_fp16.h>

#define S_LEN   2048
#define DMODEL  1024
#define NHEAD   16
#define HDIM    64
#define BATCH   2
#define M_ROWS  (BATCH * S_LEN)   /* 4096 */

// Scratch (allocation-free rule: __device__ globals).
__device__ float g_Q[BATCH * NHEAD * S_LEN * HDIM];
__device__ float g_K[BATCH * NHEAD * S_LEN * HDIM];
__device__ float g_V[BATCH * NHEAD * S_LEN * HDIM];
__device__ float g_attn[BATCH * S_LEN * DMODEL];
// Pre-packed weights: per W, 1024 rows x 512 words (bf16x2, k-pairs), hi & lo.
#define WPK (DMODEL * (DMODEL / 2))
__device__ unsigned g_Wh[4 * WPK];
__device__ unsigned g_Wl[4 * WPK];

// ---------------------------------------------------------------------------
// helpers
// ---------------------------------------------------------------------------
__device__ __forceinline__ void mma16bf(float* d, const unsigned* a, const unsigned* b) {
    asm volatile(
        "mma.sync.aligned.m16n8k16.row.col.f32.bf16.bf16.f32 "
        "{%0,%1,%2,%3}, {%4,%5,%6,%7}, {%8,%9}, {%0,%1,%2,%3};\n"
        : "+f"(d[0]), "+f"(d[1]), "+f"(d[2]), "+f"(d[3])
        : "r"(a[0]), "r"(a[1]), "r"(a[2]), "r"(a[3]), "r"(b[0]), "r"(b[1]));
}

__device__ __forceinline__ void mma16h(float* d, const unsigned* a, const unsigned* b) {
    asm volatile(
        "mma.sync.aligned.m16n8k16.row.col.f32.f16.f16.f32 "
        "{%0,%1,%2,%3}, {%4,%5,%6,%7}, {%8,%9}, {%0,%1,%2,%3};\n"
        : "+f"(d[0]), "+f"(d[1]), "+f"(d[2]), "+f"(d[3])
        : "r"(a[0]), "r"(a[1]), "r"(a[2]), "r"(a[3]), "r"(b[0]), "r"(b[1]));
}

__device__ __forceinline__ void ldsm4(unsigned* r, unsigned addr) {
    asm volatile(
        "ldmatrix.sync.aligned.m8n8.x4.shared.b16 {%0,%1,%2,%3}, [%4];"
        : "=r"(r[0]), "=r"(r[1]), "=r"(r[2]), "=r"(r[3]) : "r"(addr));
}

__device__ __forceinline__ unsigned bfpack(float lo_k, float hi_k) {
    __nv_bfloat162 t = __floats2bfloat162_rn(lo_k, hi_k);  // .x = even k (low)
    return *(unsigned*)&t;
}

__device__ __forceinline__ unsigned hpack(float lo_k, float hi_k) {
    __half2 t = __floats2half2_rn(lo_k, hi_k);             // .x = even k (low)
    return *(unsigned*)&t;
}

__device__ __forceinline__ unsigned smem_u32(const void* p) {
    return (unsigned)__cvta_generic_to_shared(p);
}

// ---------------------------------------------------------------------------
// W pre-pack: W[1024x1024] fp32 -> hi/lo bf16 k-pair words [1024x512].
// ---------------------------------------------------------------------------
__global__ __launch_bounds__(256) void pack_w_kernel(
    const float* __restrict__ W, unsigned* __restrict__ Wh,
    unsigned* __restrict__ Wl)
{
    const int i = blockIdx.x * 256 + threadIdx.x;   // word index 0..WPK-1
    float2 v = *(const float2*)(W + (size_t)i * 2);
    float h0 = __bfloat162float(__float2bfloat16_rn(v.x));
    float h1 = __bfloat162float(__float2bfloat16_rn(v.y));
    Wh[i] = bfpack(h0, h1);
    Wl[i] = bfpack(v.x - h0, v.y - h1);
}

// ---------------------------------------------------------------------------
// 3xbf16-split GEMM + bias:  C[m,n] = sum_k A[m,k] * W[n,k] + bias[n]
// CTA tile 128x128, BK=16, 256 threads (8 warps, 2Mx4N, warp tile 64x32).
// A converted in-kernel; W pre-packed (hi/lo) in gmem.
// headsplit=1: write C to [B,H,S,64]; else flat [m,1024].
// ---------------------------------------------------------------------------
#define GW 12   /* smem row stride in 32-bit words (8 words data + 4 pad) */

__global__ __launch_bounds__(256) void gemm_bf16_kernel(
    const float* __restrict__ A, const unsigned* __restrict__ Whi,
    const unsigned* __restrict__ Wlo,
    const float* __restrict__ bias, float* __restrict__ C, int headsplit)
{
    __shared__ unsigned Ah[128 * GW], Al[128 * GW];
    __shared__ unsigned Bh[128 * GW], Bl[128 * GW];

    const int tid  = threadIdx.x;
    const int lane = tid & 31;
    const int wid  = tid >> 5;
    const int wm   = wid >> 2;        // 0..1  -> 64 rows
    const int wn   = wid & 3;         // 0..3  -> 32 cols
    const int g    = lane >> 2;       // 0..7
    const int c    = lane & 3;        // 0..3
    const int bm   = blockIdx.x;
    const int bn   = blockIdx.y;

    const int lrow = tid >> 1;        // 0..127
    const int lk   = (tid & 1) << 3;  // float-k offset: 0 or 8
    const int wbase = lrow * GW + (lk >> 1);  // word offset: 0 or 4

    const float*    Ap = A   + (size_t)(bm * 128 + lrow) * DMODEL + lk;
    const unsigned* Whp = Whi + (size_t)(bn * 128 + lrow) * (DMODEL / 2) + (lk >> 1);
    const unsigned* Wlp = Wlo + (size_t)(bn * 128 + lrow) * (DMODEL / 2) + (lk >> 1);

    float acc[4][4][4];
#pragma unroll
    for (int i = 0; i < 4; i++)
#pragma unroll
        for (int j = 0; j < 4; j++)
#pragma unroll
            for (int k = 0; k < 4; k++) acc[i][j][k] = 0.f;

    float4 rA0 = *(const float4*)(Ap);
    float4 rA1 = *(const float4*)(Ap + 4);
    uint4  rWh = *(const uint4*)(Whp);
    uint4  rWl = *(const uint4*)(Wlp);

    for (int k0 = 0; k0 < DMODEL; k0 += 16) {
        float va[8] = {rA0.x, rA0.y, rA0.z, rA0.w, rA1.x, rA1.y, rA1.z, rA1.w};
        float hafl[8];
        unsigned ha[4], la[4];
#pragma unroll
        for (int i = 0; i < 8; i++)
            hafl[i] = __bfloat162float(__float2bfloat16_rn(va[i]));
#pragma unroll
        for (int i = 0; i < 4; i++) {
            ha[i] = bfpack(hafl[2*i], hafl[2*i+1]);
            la[i] = bfpack(va[2*i] - hafl[2*i], va[2*i+1] - hafl[2*i+1]);
        }

        __syncthreads();   // previous iteration's fragment reads done
        *(uint4*)&Ah[wbase] = make_uint4(ha[0], ha[1], ha[2], ha[3]);
        *(uint4*)&Al[wbase] = make_uint4(la[0], la[1], la[2], la[3]);
        *(uint4*)&Bh[wbase] = rWh;
        *(uint4*)&Bl[wbase] = rWl;
        __syncthreads();

        if (k0 + 16 < DMODEL) {
            rA0 = *(const float4*)(Ap + k0 + 16);
            rA1 = *(const float4*)(Ap + k0 + 20);
            rWh = *(const uint4*)(Whp + ((k0 + 16) >> 1));
            rWl = *(const uint4*)(Wlp + ((k0 + 16) >> 1));
        }

        unsigned ah[4][4], al[4][4], bh[4][2], bl[4][2];
#pragma unroll
        for (int ma = 0; ma < 4; ma++) {
            const int r  = wm * 64 + ma * 16 + g;
            const int b0 = r * GW + c;
            const int b1 = (r + 8) * GW + c;
            ah[ma][0] = Ah[b0]; ah[ma][1] = Ah[b1];
            ah[ma][2] = Ah[b0 + 4]; ah[ma][3] = Ah[b1 + 4];
            al[ma][0] = Al[b0]; al[ma][1] = Al[b1];
            al[ma][2] = Al[b0 + 4]; al[ma][3] = Al[b1 + 4];
        }
#pragma unroll
        for (int na = 0; na < 4; na++) {
            const int nb = (wn * 32 + na * 8 + g) * GW + c;
            bh[na][0] = Bh[nb]; bh[na][1] = Bh[nb + 4];
            bl[na][0] = Bl[nb]; bl[na][1] = Bl[nb + 4];
        }
#pragma unroll
        for (int ma = 0; ma < 4; ma++)
#pragma unroll
            for (int na = 0; na < 4; na++) {
                mma16bf(acc[ma][na], ah[ma], bl[na]);
                mma16bf(acc[ma][na], al[ma], bh[na]);
                mma16bf(acc[ma][na], ah[ma], bh[na]);
            }
    }

    // epilogue
#pragma unroll
    for (int ma = 0; ma < 4; ma++) {
        const int m0 = bm * 128 + wm * 64 + ma * 16 + g;
#pragma unroll
        for (int na = 0; na < 4; na++) {
            const int n  = bn * 128 + wn * 32 + na * 8 + (c << 1);
            const float b0 = bias[n], b1 = bias[n + 1];
            float2 v0 = make_float2(acc[ma][na][0] + b0, acc[ma][na][1] + b1);
            float2 v1 = make_float2(acc[ma][na][2] + b0, acc[ma][na][3] + b1);
            if (headsplit) {
                const int h = n >> 6, d = n & 63;
                const int b_0 = m0 >> 11, s_0 = m0 & (S_LEN - 1);
                const int b_1 = (m0 + 8) >> 11, s_1 = (m0 + 8) & (S_LEN - 1);
                *(float2*)&C[((size_t)((b_0 * NHEAD + h) * S_LEN + s_0)) * HDIM + d] = v0;
                *(float2*)&C[((size_t)((b_1 * NHEAD + h) * S_LEN + s_1)) * HDIM + d] = v1;
            } else {
                *(float2*)&C[(size_t)m0 * DMODEL + n]       = v0;
                *(float2*)&C[(size_t)(m0 + 8) * DMODEL + n] = v1;
            }
        }
    }
}

// ---------------------------------------------------------------------------
// Flash attention, fp16 MMA + ldmatrix, 32 q-rows per warp.
// grid = (16 qtiles of 128 rows, B*H=32). 128 threads = 4 warps x 32 rows.
// Each K/V ldmatrix feeds 2 m-tiles -> B-operand smem traffic per MMA halved.
// Ks: [key][d-pair words], Vs: [d][key-pair words], Ps: [qrow][key-pair words]
// ---------------------------------------------------------------------------
#define KW 36   /* word stride: 32 data + 4 pad */

__global__ __launch_bounds__(128) void attn_fp16_kernel(
    const float* __restrict__ Q, const float* __restrict__ K,
    const float* __restrict__ V, float* __restrict__ Out)
{
    __shared__ unsigned Ks[64 * KW];
    __shared__ unsigned Vs[64 * KW];
    __shared__ unsigned Ps[128 * KW];

    const int tid  = threadIdx.x;
    const int lane = tid & 31;
    const int w    = tid >> 5;
    const int g    = lane >> 2;
    const int c    = lane & 3;
    const int qtile = blockIdx.x;
    const int bh    = blockIdx.y;

    const unsigned ks_b = smem_u32(Ks), vs_b = smem_u32(Vs), ps_b = smem_u32(Ps);
    // B-operand ldmatrix lane offset
    const unsigned off_b =
        ((unsigned)(((lane >> 4) * 8 + (lane & 7)) * KW + ((lane >> 3) & 1) * 4)) * 4u;
    // A-operand (P) ldmatrix lane offset, base row w*32 (+ mt*16 added later)
    const unsigned off_a =
        ((unsigned)((w * 32 + ((lane >> 3) & 1) * 8 + (lane & 7)) * KW
                    + (lane >> 4) * 4)) * 4u;

    // Q fragments (fp16, pre-scaled by 1/8): 2 m-tiles x 4 k-steps x 4 regs
    unsigned qa[2][4][4];
#pragma unroll
    for (int mt = 0; mt < 2; mt++) {
        const float* Qb = Q + ((size_t)bh * S_LEN + qtile * 128 + w * 32 + mt * 16) * HDIM;
#pragma unroll
        for (int ks = 0; ks < 4; ks++) {
            const int d0 = ks * 16 + 2 * c;
            qa[mt][ks][0] = hpack(0.125f * Qb[(size_t)g * HDIM + d0],
                                  0.125f * Qb[(size_t)g * HDIM + d0 + 1]);
            qa[mt][ks][1] = hpack(0.125f * Qb[(size_t)(g + 8) * HDIM + d0],
                                  0.125f * Qb[(size_t)(g + 8) * HDIM + d0 + 1]);
            qa[mt][ks][2] = hpack(0.125f * Qb[(size_t)g * HDIM + d0 + 8],
                                  0.125f * Qb[(size_t)g * HDIM + d0 + 9]);
            qa[mt][ks][3] = hpack(0.125f * Qb[(size_t)(g + 8) * HDIM + d0 + 8],
                                  0.125f * Qb[(size_t)(g + 8) * HDIM + d0 + 9]);
        }
    }

    float oacc[2][8][4];
#pragma unroll
    for (int mt = 0; mt < 2; mt++)
#pragma unroll
        for (int i = 0; i < 8; i++)
#pragma unroll
            for (int j = 0; j < 4; j++) oacc[mt][i][j] = 0.f;
    // row groups: 0: mt0 rows g, 1: mt0 rows g+8, 2: mt1 rows g, 3: mt1 rows g+8
    float mrow[4] = {-1e30f, -1e30f, -1e30f, -1e30f};
    float lrow[4] = {0.f, 0.f, 0.f, 0.f};

    const float* Kb = K + (size_t)bh * S_LEN * HDIM;
    const float* Vb = V + (size_t)bh * S_LEN * HDIM;

    for (int kt = 0; kt < S_LEN / 64; kt++) {
        // ---- K tile: [key][d] -> fp16 d-pairs, row=key ----
        const float4* ksrc = (const float4*)(Kb + (size_t)kt * 64 * HDIM);
#pragma unroll
        for (int i = 0; i < 8; i++) {
            const int f   = tid + i * 128;
            const int row = f >> 4;
            const int wcol = (f & 15) * 2;
            float4 kv = ksrc[f];
            *(uint2*)&Ks[row * KW + wcol] =
                make_uint2(hpack(kv.x, kv.y), hpack(kv.z, kv.w));
        }
        // ---- V tile: transpose-pack -> row=d, words=key-pairs ----
        const float4* vsrc = (const float4*)(Vb + (size_t)kt * 64 * HDIM);
#pragma unroll
        for (int i = 0; i < 4; i++) {
            const int kp = lane;               // key pair 0..31
            const int dg = w + i * 4;          // d group of 4: 0..15
            float4 v0 = vsrc[(2 * kp) * 16 + dg];
            float4 v1 = vsrc[(2 * kp + 1) * 16 + dg];
            Vs[(dg * 4 + 0) * KW + kp] = hpack(v0.x, v1.x);
            Vs[(dg * 4 + 1) * KW + kp] = hpack(v0.y, v1.y);
            Vs[(dg * 4 + 2) * KW + kp] = hpack(v0.z, v1.z);
            Vs[(dg * 4 + 3) * KW + kp] = hpack(v0.w, v1.w);
        }
        __syncthreads();

        // ---- S = (Q/8) @ K^T : one K ldsm feeds both m-tiles ----
        float sacc[2][8][4];
#pragma unroll
        for (int mt = 0; mt < 2; mt++)
#pragma unroll
            for (int i = 0; i < 8; i++)
#pragma unroll
                for (int j = 0; j < 4; j++) sacc[mt][i][j] = 0.f;
#pragma unroll
        for (int ks = 0; ks < 4; ks++) {
#pragma unroll
            for (int p = 0; p < 4; p++) {
                unsigned kb[4];
                ldsm4(kb, ks_b + (unsigned)(p * 16 * KW + ks * 8) * 4u + off_b);
#pragma unroll
                for (int mt = 0; mt < 2; mt++) {
                    mma16h(sacc[mt][2 * p],     qa[mt][ks], kb);
                    mma16h(sacc[mt][2 * p + 1], qa[mt][ks], kb + 2);
                }
            }
        }

        // ---- online softmax (4 row groups) ----
        float tm[4] = {-1e30f, -1e30f, -1e30f, -1e30f};
#pragma unroll
        for (int mt = 0; mt < 2; mt++)
#pragma unroll
            for (int na = 0; na < 8; na++) {
                tm[2 * mt]     = fmaxf(tm[2 * mt],
                                       fmaxf(sacc[mt][na][0], sacc[mt][na][1]));
                tm[2 * mt + 1] = fmaxf(tm[2 * mt + 1],
                                       fmaxf(sacc[mt][na][2], sacc[mt][na][3]));
            }
        float mn[4], alpha[4];
#pragma unroll
        for (int rg = 0; rg < 4; rg++) {
            tm[rg] = fmaxf(tm[rg], __shfl_xor_sync(0xffffffffu, tm[rg], 1));
            tm[rg] = fmaxf(tm[rg], __shfl_xor_sync(0xffffffffu, tm[rg], 2));
            mn[rg] = fmaxf(mrow[rg], tm[rg]);
            alpha[rg] = __expf(mrow[rg] - mn[rg]);
            mrow[rg] = mn[rg];
        }

        float rs[4] = {0.f, 0.f, 0.f, 0.f};
#pragma unroll
        for (int mt = 0; mt < 2; mt++) {
            const int pr0 = (w * 32 + mt * 16 + g) * KW;
            const int pr1 = pr0 + 8 * KW;
#pragma unroll
            for (int na = 0; na < 8; na++) {
                const float p0 = __expf(sacc[mt][na][0] - mn[2 * mt]);
                const float p1 = __expf(sacc[mt][na][1] - mn[2 * mt]);
                const float p2 = __expf(sacc[mt][na][2] - mn[2 * mt + 1]);
                const float p3 = __expf(sacc[mt][na][3] - mn[2 * mt + 1]);
                rs[2 * mt]     += p0 + p1;
                rs[2 * mt + 1] += p2 + p3;
                Ps[pr0 + na * 4 + c] = hpack(p0, p1);
                Ps[pr1 + na * 4 + c] = hpack(p2, p3);
            }
        }
#pragma unroll
        for (int rg = 0; rg < 4; rg++) {
            rs[rg] += __shfl_xor_sync(0xffffffffu, rs[rg], 1);
            rs[rg] += __shfl_xor_sync(0xffffffffu, rs[rg], 2);
            lrow[rg] = lrow[rg] * alpha[rg] + rs[rg];
        }
#pragma unroll
        for (int mt = 0; mt < 2; mt++)
#pragma unroll
            for (int na = 0; na < 8; na++) {
                oacc[mt][na][0] *= alpha[2 * mt];
                oacc[mt][na][1] *= alpha[2 * mt];
                oacc[mt][na][2] *= alpha[2 * mt + 1];
                oacc[mt][na][3] *= alpha[2 * mt + 1];
            }
        __syncwarp();   // Ps rows are warp-private

        // ---- O += P @ V : one V ldsm feeds both m-tiles ----
#pragma unroll
        for (int ks = 0; ks < 4; ks++) {
            unsigned pa[2][4];
            ldsm4(pa[0], ps_b + (unsigned)(ks * 8) * 4u + off_a);
            ldsm4(pa[1], ps_b + (unsigned)(16 * KW + ks * 8) * 4u + off_a);
#pragma unroll
            for (int p = 0; p < 4; p++) {
                unsigned vb[4];
                ldsm4(vb, vs_b + (unsigned)(p * 16 * KW + ks * 8) * 4u + off_b);
#pragma unroll
                for (int mt = 0; mt < 2; mt++) {
                    mma16h(oacc[mt][2 * p],     pa[mt], vb);
                    mma16h(oacc[mt][2 * p + 1], pa[mt], vb + 2);
                }
            }
        }
        __syncthreads();   // all reads done before next tile's stores
    }

    // ---- epilogue ----
    const int b = bh >> 4, h = bh & 15;
#pragma unroll
    for (int mt = 0; mt < 2; mt++) {
        const float inv0 = 1.f / lrow[2 * mt];
        const float inv1 = 1.f / lrow[2 * mt + 1];
        const int s0 = qtile * 128 + w * 32 + mt * 16 + g;
        float* o0 = Out + ((size_t)(b * S_LEN + s0)) * DMODEL + h * HDIM;
        float* o1 = o0 + (size_t)8 * DMODEL;
#pragma unroll
        for (int na = 0; na < 8; na++) {
            const int col = na * 8 + (c << 1);
            *(float2*)(o0 + col) = make_float2(oacc[mt][na][0] * inv0,
                                               oacc[mt][na][1] * inv0);
            *(float2*)(o1 + col) = make_float2(oacc[mt][na][2] * inv1,
                                               oacc[mt][na][3] * inv1);
        }
    }
}

// ---------------------------------------------------------------------------
extern "C" void kernel_launch(void* const* d_in, const int* in_sizes, int n_in,
                              void* d_out, int out_size)
{
    const float* query = (const float*)d_in[0];
    const float* key   = (const float*)d_in[1];
    const float* value = (const float*)d_in[2];
    const float* Wq = (const float*)d_in[3];
    const float* bq = (const float*)d_in[4];
    const float* Wk = (const float*)d_in[5];
    const float* bk = (const float*)d_in[6];
    const float* Wv = (const float*)d_in[7];
    const float* bv = (const float*)d_in[8];
    const float* Wo = (const float*)d_in[9];
    const float* bo = (const float*)d_in[10];
    float* out = (float*)d_out;

    float *pQ, *pK, *pV, *pA;
    unsigned *pWh, *pWl;
    cudaGetSymbolAddress((void**)&pQ, g_Q);
    cudaGetSymbolAddress((void**)&pK, g_K);
    cudaGetSymbolAddress((void**)&pV, g_V);
    cudaGetSymbolAddress((void**)&pA, g_attn);
    cudaGetSymbolAddress((void**)&pWh, g_Wh);
    cudaGetSymbolAddress((void**)&pWl, g_Wl);

    // pack the four weight matrices (hi/lo bf16 k-pair words)
    const int pgrid = WPK / 256;
    pack_w_kernel<<<pgrid, 256>>>(Wq, pWh + 0 * WPK, pWl + 0 * WPK);
    pack_w_kernel<<<pgrid, 256>>>(Wk, pWh + 1 * WPK, pWl + 1 * WPK);
    pack_w_kernel<<<pgrid, 256>>>(Wv, pWh + 2 * WPK, pWl + 2 * WPK);
    pack_w_kernel<<<pgrid, 256>>>(Wo, pWh + 3 * WPK, pWl + 3 * WPK);

    dim3 ggrid(M_ROWS / 128, DMODEL / 128);
    gemm_bf16_kernel<<<ggrid, 256>>>(query, pWh + 0 * WPK, pWl + 0 * WPK, bq, pQ, 1);
    gemm_bf16_kernel<<<ggrid, 256>>>(key,   pWh + 1 * WPK, pWl + 1 * WPK, bk, pK, 1);
    gemm_bf16_kernel<<<ggrid, 256>>>(value, pWh + 2 * WPK, pWl + 2 * WPK, bv, pV, 1);

    dim3 agrid(S_LEN / 128, BATCH * NHEAD);
    attn_fp16_kernel<<<agrid, 128>>>(pQ, pK, pV, pA);

    gemm_bf16_kernel<<<ggrid, 256>>>(pA, pWh + 3 * WPK, pWl + 3 * WPK, bo, out, 0);
}

// round 8
// speedup vs baseline: 1.6883x; 1.4791x over previous
#include <cuda_runtime.h>
#include <cuda_bf16.h>
#include <cuda_fp16.h>

#define S_LEN   2048
#define DMODEL  1024
#define NHEAD   16
#define HDIM    64
#define BATCH   2
#define M_ROWS  (BATCH * S_LEN)   /* 4096 */

// Scratch (allocation-free rule: __device__ globals).
__device__ float g_Q[BATCH * NHEAD * S_LEN * HDIM];
__device__ float g_K[BATCH * NHEAD * S_LEN * HDIM];
__device__ float g_V[BATCH * NHEAD * S_LEN * HDIM];
__device__ float g_attn[BATCH * S_LEN * DMODEL];
// Pre-packed weights: per W, 1024 rows x 512 words (fp16x2 k-pairs).
#define WPK (DMODEL * (DMODEL / 2))
__device__ unsigned g_Wh[4 * WPK];

// ---------------------------------------------------------------------------
// helpers
// ---------------------------------------------------------------------------
__device__ __forceinline__ void mma16h(float* d, const unsigned* a, const unsigned* b) {
    asm volatile(
        "mma.sync.aligned.m16n8k16.row.col.f32.f16.f16.f32 "
        "{%0,%1,%2,%3}, {%4,%5,%6,%7}, {%8,%9}, {%0,%1,%2,%3};\n"
        : "+f"(d[0]), "+f"(d[1]), "+f"(d[2]), "+f"(d[3])
        : "r"(a[0]), "r"(a[1]), "r"(a[2]), "r"(a[3]), "r"(b[0]), "r"(b[1]));
}

__device__ __forceinline__ void ldsm4(unsigned* r, unsigned addr) {
    asm volatile(
        "ldmatrix.sync.aligned.m8n8.x4.shared.b16 {%0,%1,%2,%3}, [%4];"
        : "=r"(r[0]), "=r"(r[1]), "=r"(r[2]), "=r"(r[3]) : "r"(addr));
}

__device__ __forceinline__ unsigned hpack(float lo_k, float hi_k) {
    __half2 t = __floats2half2_rn(lo_k, hi_k);             // .x = even k (low)
    return *(unsigned*)&t;
}

__device__ __forceinline__ unsigned smem_u32(const void* p) {
    return (unsigned)__cvta_generic_to_shared(p);
}

// ---------------------------------------------------------------------------
// W pre-pack: W[1024x1024] fp32 -> fp16 k-pair words [1024x512].
// ---------------------------------------------------------------------------
__global__ __launch_bounds__(256) void pack_w_kernel(
    const float* __restrict__ W, unsigned* __restrict__ Wh)
{
    const int i = blockIdx.x * 256 + threadIdx.x;   // word index 0..WPK-1
    float2 v = *(const float2*)(W + (size_t)i * 2);
    Wh[i] = hpack(v.x, v.y);
}

// ---------------------------------------------------------------------------
// fp16 GEMM + bias:  C[m,n] = sum_k A[m,k] * W[n,k] + bias[n]  (f32 accum)
// CTA tile 128x128, BK=16, 256 threads (8 warps, 2Mx4N, warp tile 64x32).
// A converted to fp16 in-kernel; W pre-packed fp16 in gmem.
// headsplit=1: write C to [B,H,S,64]; else flat [m,1024].
// ---------------------------------------------------------------------------
#define GW 12   /* smem row stride in 32-bit words (8 words data + 4 pad) */

__global__ __launch_bounds__(256) void gemm_fp16_kernel(
    const float* __restrict__ A, const unsigned* __restrict__ Whi,
    const float* __restrict__ bias, float* __restrict__ C, int headsplit)
{
    __shared__ unsigned Ah[128 * GW];
    __shared__ unsigned Bh[128 * GW];

    const int tid  = threadIdx.x;
    const int lane = tid & 31;
    const int wid  = tid >> 5;
    const int wm   = wid >> 2;        // 0..1  -> 64 rows
    const int wn   = wid & 3;         // 0..3  -> 32 cols
    const int g    = lane >> 2;       // 0..7
    const int c    = lane & 3;        // 0..3
    const int bm   = blockIdx.x;
    const int bn   = blockIdx.y;

    const int lrow = tid >> 1;        // 0..127
    const int lk   = (tid & 1) << 3;  // float-k offset: 0 or 8
    const int wbase = lrow * GW + (lk >> 1);  // word offset: 0 or 4

    const float*    Ap  = A   + (size_t)(bm * 128 + lrow) * DMODEL + lk;
    const unsigned* Whp = Whi + (size_t)(bn * 128 + lrow) * (DMODEL / 2) + (lk >> 1);

    float acc[4][4][4];
#pragma unroll
    for (int i = 0; i < 4; i++)
#pragma unroll
        for (int j = 0; j < 4; j++)
#pragma unroll
            for (int k = 0; k < 4; k++) acc[i][j][k] = 0.f;

    float4 rA0 = *(const float4*)(Ap);
    float4 rA1 = *(const float4*)(Ap + 4);
    uint4  rWh = *(const uint4*)(Whp);

    for (int k0 = 0; k0 < DMODEL; k0 += 16) {
        const unsigned a0 = hpack(rA0.x, rA0.y);
        const unsigned a1 = hpack(rA0.z, rA0.w);
        const unsigned a2 = hpack(rA1.x, rA1.y);
        const unsigned a3 = hpack(rA1.z, rA1.w);

        __syncthreads();   // previous iteration's fragment reads done
        *(uint4*)&Ah[wbase] = make_uint4(a0, a1, a2, a3);
        *(uint4*)&Bh[wbase] = rWh;
        __syncthreads();

        if (k0 + 16 < DMODEL) {
            rA0 = *(const float4*)(Ap + k0 + 16);
            rA1 = *(const float4*)(Ap + k0 + 20);
            rWh = *(const uint4*)(Whp + ((k0 + 16) >> 1));
        }

        unsigned ah[4][4], bh[4][2];
#pragma unroll
        for (int ma = 0; ma < 4; ma++) {
            const int r  = wm * 64 + ma * 16 + g;
            const int b0 = r * GW + c;
            const int b1 = (r + 8) * GW + c;
            ah[ma][0] = Ah[b0]; ah[ma][1] = Ah[b1];
            ah[ma][2] = Ah[b0 + 4]; ah[ma][3] = Ah[b1 + 4];
        }
#pragma unroll
        for (int na = 0; na < 4; na++) {
            const int nb = (wn * 32 + na * 8 + g) * GW + c;
            bh[na][0] = Bh[nb]; bh[na][1] = Bh[nb + 4];
        }
#pragma unroll
        for (int ma = 0; ma < 4; ma++)
#pragma unroll
            for (int na = 0; na < 4; na++)
                mma16h(acc[ma][na], ah[ma], bh[na]);
    }

    // epilogue
#pragma unroll
    for (int ma = 0; ma < 4; ma++) {
        const int m0 = bm * 128 + wm * 64 + ma * 16 + g;
#pragma unroll
        for (int na = 0; na < 4; na++) {
            const int n  = bn * 128 + wn * 32 + na * 8 + (c << 1);
            const float b0 = bias[n], b1 = bias[n + 1];
            float2 v0 = make_float2(acc[ma][na][0] + b0, acc[ma][na][1] + b1);
            float2 v1 = make_float2(acc[ma][na][2] + b0, acc[ma][na][3] + b1);
            if (headsplit) {
                const int h = n >> 6, d = n & 63;
                const int b_0 = m0 >> 11, s_0 = m0 & (S_LEN - 1);
                const int b_1 = (m0 + 8) >> 11, s_1 = (m0 + 8) & (S_LEN - 1);
                *(float2*)&C[((size_t)((b_0 * NHEAD + h) * S_LEN + s_0)) * HDIM + d] = v0;
                *(float2*)&C[((size_t)((b_1 * NHEAD + h) * S_LEN + s_1)) * HDIM + d] = v1;
            } else {
                *(float2*)&C[(size_t)m0 * DMODEL + n]       = v0;
                *(float2*)&C[(size_t)(m0 + 8) * DMODEL + n] = v1;
            }
        }
    }
}

// ---------------------------------------------------------------------------
// Flash attention, fp16 MMA + ldmatrix, 32 q-rows per warp.
// grid = (16 qtiles of 128 rows, B*H=32). 128 threads = 4 warps x 32 rows.
// (unchanged from round 6 — known good)
// ---------------------------------------------------------------------------
#define KW 36   /* word stride: 32 data + 4 pad */

__global__ __launch_bounds__(128) void attn_fp16_kernel(
    const float* __restrict__ Q, const float* __restrict__ K,
    const float* __restrict__ V, float* __restrict__ Out)
{
    __shared__ unsigned Ks[64 * KW];
    __shared__ unsigned Vs[64 * KW];
    __shared__ unsigned Ps[128 * KW];

    const int tid  = threadIdx.x;
    const int lane = tid & 31;
    const int w    = tid >> 5;
    const int g    = lane >> 2;
    const int c    = lane & 3;
    const int qtile = blockIdx.x;
    const int bh    = blockIdx.y;

    const unsigned ks_b = smem_u32(Ks), vs_b = smem_u32(Vs), ps_b = smem_u32(Ps);
    const unsigned off_b =
        ((unsigned)(((lane >> 4) * 8 + (lane & 7)) * KW + ((lane >> 3) & 1) * 4)) * 4u;
    const unsigned off_a =
        ((unsigned)((w * 32 + ((lane >> 3) & 1) * 8 + (lane & 7)) * KW
                    + (lane >> 4) * 4)) * 4u;

    // Q fragments (fp16, pre-scaled by 1/8): 2 m-tiles x 4 k-steps x 4 regs
    unsigned qa[2][4][4];
#pragma unroll
    for (int mt = 0; mt < 2; mt++) {
        const float* Qb = Q + ((size_t)bh * S_LEN + qtile * 128 + w * 32 + mt * 16) * HDIM;
#pragma unroll
        for (int ks = 0; ks < 4; ks++) {
            const int d0 = ks * 16 + 2 * c;
            qa[mt][ks][0] = hpack(0.125f * Qb[(size_t)g * HDIM + d0],
                                  0.125f * Qb[(size_t)g * HDIM + d0 + 1]);
            qa[mt][ks][1] = hpack(0.125f * Qb[(size_t)(g + 8) * HDIM + d0],
                                  0.125f * Qb[(size_t)(g + 8) * HDIM + d0 + 1]);
            qa[mt][ks][2] = hpack(0.125f * Qb[(size_t)g * HDIM + d0 + 8],
                                  0.125f * Qb[(size_t)g * HDIM + d0 + 9]);
            qa[mt][ks][3] = hpack(0.125f * Qb[(size_t)(g + 8) * HDIM + d0 + 8],
                                  0.125f * Qb[(size_t)(g + 8) * HDIM + d0 + 9]);
        }
    }

    float oacc[2][8][4];
#pragma unroll
    for (int mt = 0; mt < 2; mt++)
#pragma unroll
        for (int i = 0; i < 8; i++)
#pragma unroll
            for (int j = 0; j < 4; j++) oacc[mt][i][j] = 0.f;
    float mrow[4] = {-1e30f, -1e30f, -1e30f, -1e30f};
    float lrow[4] = {0.f, 0.f, 0.f, 0.f};

    const float* Kb = K + (size_t)bh * S_LEN * HDIM;
    const float* Vb = V + (size_t)bh * S_LEN * HDIM;

    for (int kt = 0; kt < S_LEN / 64; kt++) {
        const float4* ksrc = (const float4*)(Kb + (size_t)kt * 64 * HDIM);
#pragma unroll
        for (int i = 0; i < 8; i++) {
            const int f   = tid + i * 128;
            const int row = f >> 4;
            const int wcol = (f & 15) * 2;
            float4 kv = ksrc[f];
            *(uint2*)&Ks[row * KW + wcol] =
                make_uint2(hpack(kv.x, kv.y), hpack(kv.z, kv.w));
        }
        const float4* vsrc = (const float4*)(Vb + (size_t)kt * 64 * HDIM);
#pragma unroll
        for (int i = 0; i < 4; i++) {
            const int kp = lane;
            const int dg = w + i * 4;
            float4 v0 = vsrc[(2 * kp) * 16 + dg];
            float4 v1 = vsrc[(2 * kp + 1) * 16 + dg];
            Vs[(dg * 4 + 0) * KW + kp] = hpack(v0.x, v1.x);
            Vs[(dg * 4 + 1) * KW + kp] = hpack(v0.y, v1.y);
            Vs[(dg * 4 + 2) * KW + kp] = hpack(v0.z, v1.z);
            Vs[(dg * 4 + 3) * KW + kp] = hpack(v0.w, v1.w);
        }
        __syncthreads();

        float sacc[2][8][4];
#pragma unroll
        for (int mt = 0; mt < 2; mt++)
#pragma unroll
            for (int i = 0; i < 8; i++)
#pragma unroll
                for (int j = 0; j < 4; j++) sacc[mt][i][j] = 0.f;
#pragma unroll
        for (int ks = 0; ks < 4; ks++) {
#pragma unroll
            for (int p = 0; p < 4; p++) {
                unsigned kb[4];
                ldsm4(kb, ks_b + (unsigned)(p * 16 * KW + ks * 8) * 4u + off_b);
#pragma unroll
                for (int mt = 0; mt < 2; mt++) {
                    mma16h(sacc[mt][2 * p],     qa[mt][ks], kb);
                    mma16h(sacc[mt][2 * p + 1], qa[mt][ks], kb + 2);
                }
            }
        }

        float tm[4] = {-1e30f, -1e30f, -1e30f, -1e30f};
#pragma unroll
        for (int mt = 0; mt < 2; mt++)
#pragma unroll
            for (int na = 0; na < 8; na++) {
                tm[2 * mt]     = fmaxf(tm[2 * mt],
                                       fmaxf(sacc[mt][na][0], sacc[mt][na][1]));
                tm[2 * mt + 1] = fmaxf(tm[2 * mt + 1],
                                       fmaxf(sacc[mt][na][2], sacc[mt][na][3]));
            }
        float mn[4], alpha[4];
#pragma unroll
        for (int rg = 0; rg < 4; rg++) {
            tm[rg] = fmaxf(tm[rg], __shfl_xor_sync(0xffffffffu, tm[rg], 1));
            tm[rg] = fmaxf(tm[rg], __shfl_xor_sync(0xffffffffu, tm[rg], 2));
            mn[rg] = fmaxf(mrow[rg], tm[rg]);
            alpha[rg] = __expf(mrow[rg] - mn[rg]);
            mrow[rg] = mn[rg];
        }

        float rs[4] = {0.f, 0.f, 0.f, 0.f};
#pragma unroll
        for (int mt = 0; mt < 2; mt++) {
            const int pr0 = (w * 32 + mt * 16 + g) * KW;
            const int pr1 = pr0 + 8 * KW;
#pragma unroll
            for (int na = 0; na < 8; na++) {
                const float p0 = __expf(sacc[mt][na][0] - mn[2 * mt]);
                const float p1 = __expf(sacc[mt][na][1] - mn[2 * mt]);
                const float p2 = __expf(sacc[mt][na][2] - mn[2 * mt + 1]);
                const float p3 = __expf(sacc[mt][na][3] - mn[2 * mt + 1]);
                rs[2 * mt]     += p0 + p1;
                rs[2 * mt + 1] += p2 + p3;
                Ps[pr0 + na * 4 + c] = hpack(p0, p1);
                Ps[pr1 + na * 4 + c] = hpack(p2, p3);
            }
        }
#pragma unroll
        for (int rg = 0; rg < 4; rg++) {
            rs[rg] += __shfl_xor_sync(0xffffffffu, rs[rg], 1);
            rs[rg] += __shfl_xor_sync(0xffffffffu, rs[rg], 2);
            lrow[rg] = lrow[rg] * alpha[rg] + rs[rg];
        }
#pragma unroll
        for (int mt = 0; mt < 2; mt++)
#pragma unroll
            for (int na = 0; na < 8; na++) {
                oacc[mt][na][0] *= alpha[2 * mt];
                oacc[mt][na][1] *= alpha[2 * mt];
                oacc[mt][na][2] *= alpha[2 * mt + 1];
                oacc[mt][na][3] *= alpha[2 * mt + 1];
            }
        __syncwarp();   // Ps rows are warp-private

#pragma unroll
        for (int ks = 0; ks < 4; ks++) {
            unsigned pa[2][4];
            ldsm4(pa[0], ps_b + (unsigned)(ks * 8) * 4u + off_a);
            ldsm4(pa[1], ps_b + (unsigned)(16 * KW + ks * 8) * 4u + off_a);
#pragma unroll
            for (int p = 0; p < 4; p++) {
                unsigned vb[4];
                ldsm4(vb, vs_b + (unsigned)(p * 16 * KW + ks * 8) * 4u + off_b);
#pragma unroll
                for (int mt = 0; mt < 2; mt++) {
                    mma16h(oacc[mt][2 * p],     pa[mt], vb);
                    mma16h(oacc[mt][2 * p + 1], pa[mt], vb + 2);
                }
            }
        }
        __syncthreads();
    }

    const int b = bh >> 4, h = bh & 15;
#pragma unroll
    for (int mt = 0; mt < 2; mt++) {
        const float inv0 = 1.f / lrow[2 * mt];
        const float inv1 = 1.f / lrow[2 * mt + 1];
        const int s0 = qtile * 128 + w * 32 + mt * 16 + g;
        float* o0 = Out + ((size_t)(b * S_LEN + s0)) * DMODEL + h * HDIM;
        float* o1 = o0 + (size_t)8 * DMODEL;
#pragma unroll
        for (int na = 0; na < 8; na++) {
            const int col = na * 8 + (c << 1);
            *(float2*)(o0 + col) = make_float2(oacc[mt][na][0] * inv0,
                                               oacc[mt][na][1] * inv0);
            *(float2*)(o1 + col) = make_float2(oacc[mt][na][2] * inv1,
                                               oacc[mt][na][3] * inv1);
        }
    }
}

// ---------------------------------------------------------------------------
extern "C" void kernel_launch(void* const* d_in, const int* in_sizes, int n_in,
                              void* d_out, int out_size)
{
    const float* query = (const float*)d_in[0];
    const float* key   = (const float*)d_in[1];
    const float* value = (const float*)d_in[2];
    const float* Wq = (const float*)d_in[3];
    const float* bq = (const float*)d_in[4];
    const float* Wk = (const float*)d_in[5];
    const float* bk = (const float*)d_in[6];
    const float* Wv = (const float*)d_in[7];
    const float* bv = (const float*)d_in[8];
    const float* Wo = (const float*)d_in[9];
    const float* bo = (const float*)d_in[10];
    float* out = (float*)d_out;

    float *pQ, *pK, *pV, *pA;
    unsigned *pWh;
    cudaGetSymbolAddress((void**)&pQ, g_Q);
    cudaGetSymbolAddress((void**)&pK, g_K);
    cudaGetSymbolAddress((void**)&pV, g_V);
    cudaGetSymbolAddress((void**)&pA, g_attn);
    cudaGetSymbolAddress((void**)&pWh, g_Wh);

    // pack the four weight matrices to fp16 k-pair words
    const int pgrid = WPK / 256;
    pack_w_kernel<<<pgrid, 256>>>(Wq, pWh + 0 * WPK);
    pack_w_kernel<<<pgrid, 256>>>(Wk, pWh + 1 * WPK);
    pack_w_kernel<<<pgrid, 256>>>(Wv, pWh + 2 * WPK);
    pack_w_kernel<<<pgrid, 256>>>(Wo, pWh + 3 * WPK);

    dim3 ggrid(M_ROWS / 128, DMODEL / 128);
    gemm_fp16_kernel<<<ggrid, 256>>>(query, pWh + 0 * WPK, bq, pQ, 1);
    gemm_fp16_kernel<<<ggrid, 256>>>(key,   pWh + 1 * WPK, bk, pK, 1);
    gemm_fp16_kernel<<<ggrid, 256>>>(value, pWh + 2 * WPK, bv, pV, 1);

    dim3 agrid(S_LEN / 128, BATCH * NHEAD);
    attn_fp16_kernel<<<agrid, 128>>>(pQ, pK, pV, pA);

    gemm_fp16_kernel<<<ggrid, 256>>>(pA, pWh + 3 * WPK, bo, out, 0);
}

// round 9
// speedup vs baseline: 2.0388x; 1.2076x over previous
#include <cuda_runtime.h>
#include <cuda_fp16.h>

#define S_LEN   2048
#define DMODEL  1024
#define NHEAD   16
#define HDIM    64
#define BATCH   2
#define M_ROWS  (BATCH * S_LEN)   /* 4096 */
#define BH      (BATCH * NHEAD)   /* 32 */

// Scratch (allocation-free rule: __device__ globals).
// Packed fp16 word layouts (one unsigned = 2 fp16):
//  g_Qp/g_Kp/g_Vp : [bh][s][32 words]  (d-pairs; Q pre-scaled by 1/8)
//  g_Vt           : [bh][d(64)][S/2=1024 words] (key-pairs)
//  g_attnP        : [m][512 words]     (d_model-pairs)
__device__ unsigned g_Qp[BH * S_LEN * (HDIM / 2)];
__device__ unsigned g_Kp[BH * S_LEN * (HDIM / 2)];
__device__ unsigned g_Vp[BH * S_LEN * (HDIM / 2)];
__device__ unsigned g_Vt[BH * HDIM * (S_LEN / 2)];
__device__ unsigned g_attnP[M_ROWS * (DMODEL / 2)];
// Pre-packed weights: per W, 1024 rows x 512 words (fp16x2 k-pairs).
#define WPK (DMODEL * (DMODEL / 2))
__device__ unsigned g_Wh[4 * WPK];

// ---------------------------------------------------------------------------
// helpers
// ---------------------------------------------------------------------------
__device__ __forceinline__ void mma16h(float* d, const unsigned* a, const unsigned* b) {
    asm volatile(
        "mma.sync.aligned.m16n8k16.row.col.f32.f16.f16.f32 "
        "{%0,%1,%2,%3}, {%4,%5,%6,%7}, {%8,%9}, {%0,%1,%2,%3};\n"
        : "+f"(d[0]), "+f"(d[1]), "+f"(d[2]), "+f"(d[3])
        : "r"(a[0]), "r"(a[1]), "r"(a[2]), "r"(a[3]), "r"(b[0]), "r"(b[1]));
}

__device__ __forceinline__ void ldsm4(unsigned* r, unsigned addr) {
    asm volatile(
        "ldmatrix.sync.aligned.m8n8.x4.shared.b16 {%0,%1,%2,%3}, [%4];"
        : "=r"(r[0]), "=r"(r[1]), "=r"(r[2]), "=r"(r[3]) : "r"(addr));
}

__device__ __forceinline__ unsigned hpack(float lo_k, float hi_k) {
    __half2 t = __floats2half2_rn(lo_k, hi_k);             // .x = even k (low)
    return *(unsigned*)&t;
}

__device__ __forceinline__ unsigned smem_u32(const void* p) {
    return (unsigned)__cvta_generic_to_shared(p);
}

__device__ __forceinline__ void cpa16(unsigned dst, const void* src) {
    asm volatile("cp.async.cg.shared.global [%0], [%1], 16;\n"
                 :: "r"(dst), "l"(src));
}
__device__ __forceinline__ void cpa_commit() {
    asm volatile("cp.async.commit_group;\n");
}
__device__ __forceinline__ void cpa_wait1() {
    asm volatile("cp.async.wait_group 1;\n");
}
__device__ __forceinline__ void cpa_wait0() {
    asm volatile("cp.async.wait_group 0;\n");
}

// ---------------------------------------------------------------------------
// W pre-pack (all 4 weights in one launch): fp32 -> fp16 k-pair words.
// ---------------------------------------------------------------------------
__global__ __launch_bounds__(256) void pack_w_kernel(
    const float* __restrict__ W0, const float* __restrict__ W1,
    const float* __restrict__ W2, const float* __restrict__ W3,
    unsigned* __restrict__ Wh)
{
    const int by = blockIdx.y;
    const float* W = (by == 0) ? W0 : (by == 1) ? W1 : (by == 2) ? W2 : W3;
    const int i = blockIdx.x * 256 + threadIdx.x;   // word index 0..WPK-1
    float2 v = *(const float2*)(W + (size_t)i * 2);
    Wh[(size_t)by * WPK + i] = hpack(v.x, v.y);
}

// ---------------------------------------------------------------------------
// V transpose-pack: g_Vp [bh][key][32 d-words] -> g_Vt [bh][d][key-pair words]
// grid (S/64, BH), 256 threads; smem 64x33 tile.
// ---------------------------------------------------------------------------
__global__ __launch_bounds__(256) void vtrans_kernel(
    const unsigned* __restrict__ Vp, unsigned* __restrict__ Vt)
{
    __shared__ unsigned sT[64 * 33];
    const int t  = threadIdx.x;
    const int kt = blockIdx.x;
    const int bh = blockIdx.y;

    const unsigned* src = Vp + ((size_t)bh * S_LEN + kt * 64) * (HDIM / 2);
#pragma unroll
    for (int i = 0; i < 8; i++) {
        const int idx = t + i * 256;                 // 0..2047
        sT[(idx >> 5) * 33 + (idx & 31)] = src[idx];
    }
    __syncthreads();

    unsigned* dst = Vt + (size_t)bh * HDIM * (S_LEN / 2) + kt * 32;
#pragma unroll
    for (int i = 0; i < 8; i++) {
        const int idx = t + i * 256;
        const int kp = idx & 31;                     // key pair within tile
        const int d  = idx >> 5;                     // 0..63
        const unsigned w0 = sT[(2 * kp) * 33 + (d >> 1)];
        const unsigned w1 = sT[(2 * kp + 1) * 33 + (d >> 1)];
        dst[(size_t)d * (S_LEN / 2) + kp] =
            __byte_perm(w0, w1, (d & 1) ? 0x7632 : 0x5410);
    }
}

// ---------------------------------------------------------------------------
// fp16 GEMM + bias (fp32 A, in-kernel conversion).
// mode 0: C = float*, flat [m,1024].
// mode 1: C = unsigned*, headsplit packed fp16 [bh][s][32 words], *scale.
// ---------------------------------------------------------------------------
#define GW 12   /* smem row stride in 32-bit words (8 words data + 4 pad) */

__global__ __launch_bounds__(256) void gemm_fp16_kernel(
    const float* __restrict__ A, const unsigned* __restrict__ Whi,
    const float* __restrict__ bias, void* __restrict__ Cv,
    int mode, float scale)
{
    __shared__ unsigned Ah[128 * GW];
    __shared__ unsigned Bh[128 * GW];

    const int tid  = threadIdx.x;
    const int lane = tid & 31;
    const int wid  = tid >> 5;
    const int wm   = wid >> 2;
    const int wn   = wid & 3;
    const int g    = lane >> 2;
    const int c    = lane & 3;
    const int bm   = blockIdx.x;
    const int bn   = blockIdx.y;

    const int lrow = tid >> 1;
    const int lk   = (tid & 1) << 3;
    const int wbase = lrow * GW + (lk >> 1);

    const float*    Ap  = A   + (size_t)(bm * 128 + lrow) * DMODEL + lk;
    const unsigned* Whp = Whi + (size_t)(bn * 128 + lrow) * (DMODEL / 2) + (lk >> 1);

    float acc[4][4][4];
#pragma unroll
    for (int i = 0; i < 4; i++)
#pragma unroll
        for (int j = 0; j < 4; j++)
#pragma unroll
            for (int k = 0; k < 4; k++) acc[i][j][k] = 0.f;

    float4 rA0 = *(const float4*)(Ap);
    float4 rA1 = *(const float4*)(Ap + 4);
    uint4  rWh = *(const uint4*)(Whp);

    for (int k0 = 0; k0 < DMODEL; k0 += 16) {
        const unsigned a0 = hpack(rA0.x, rA0.y);
        const unsigned a1 = hpack(rA0.z, rA0.w);
        const unsigned a2 = hpack(rA1.x, rA1.y);
        const unsigned a3 = hpack(rA1.z, rA1.w);

        __syncthreads();
        *(uint4*)&Ah[wbase] = make_uint4(a0, a1, a2, a3);
        *(uint4*)&Bh[wbase] = rWh;
        __syncthreads();

        if (k0 + 16 < DMODEL) {
            rA0 = *(const float4*)(Ap + k0 + 16);
            rA1 = *(const float4*)(Ap + k0 + 20);
            rWh = *(const uint4*)(Whp + ((k0 + 16) >> 1));
        }

        unsigned ah[4][4], bh[4][2];
#pragma unroll
        for (int ma = 0; ma < 4; ma++) {
            const int r  = wm * 64 + ma * 16 + g;
            const int b0 = r * GW + c;
            const int b1 = (r + 8) * GW + c;
            ah[ma][0] = Ah[b0]; ah[ma][1] = Ah[b1];
            ah[ma][2] = Ah[b0 + 4]; ah[ma][3] = Ah[b1 + 4];
        }
#pragma unroll
        for (int na = 0; na < 4; na++) {
            const int nb = (wn * 32 + na * 8 + g) * GW + c;
            bh[na][0] = Bh[nb]; bh[na][1] = Bh[nb + 4];
        }
#pragma unroll
        for (int ma = 0; ma < 4; ma++)
#pragma unroll
            for (int na = 0; na < 4; na++)
                mma16h(acc[ma][na], ah[ma], bh[na]);
    }

    // epilogue
#pragma unroll
    for (int ma = 0; ma < 4; ma++) {
        const int m0 = bm * 128 + wm * 64 + ma * 16 + g;
#pragma unroll
        for (int na = 0; na < 4; na++) {
            const int n  = bn * 128 + wn * 32 + na * 8 + (c << 1);
            const float b0 = bias[n], b1 = bias[n + 1];
            const float v00 = acc[ma][na][0] + b0, v01 = acc[ma][na][1] + b1;
            const float v10 = acc[ma][na][2] + b0, v11 = acc[ma][na][3] + b1;
            if (mode) {
                unsigned* Cp = (unsigned*)Cv;
                const int h = n >> 6, dw = (n & 63) >> 1;
                const int b_0 = m0 >> 11, s_0 = m0 & (S_LEN - 1);
                const int b_1 = (m0 + 8) >> 11, s_1 = (m0 + 8) & (S_LEN - 1);
                Cp[((size_t)((b_0 * NHEAD + h) * S_LEN + s_0)) * 32 + dw] =
                    hpack(scale * v00, scale * v01);
                Cp[((size_t)((b_1 * NHEAD + h) * S_LEN + s_1)) * 32 + dw] =
                    hpack(scale * v10, scale * v11);
            } else {
                float* C = (float*)Cv;
                *(float2*)&C[(size_t)m0 * DMODEL + n]       = make_float2(v00, v01);
                *(float2*)&C[(size_t)(m0 + 8) * DMODEL + n] = make_float2(v10, v11);
            }
        }
    }
}

// ---------------------------------------------------------------------------
// fp16 GEMM, packed-fp16 A (for the O projection). Output flat fp32.
// ---------------------------------------------------------------------------
__global__ __launch_bounds__(256) void gemm_fp16_pA_kernel(
    const unsigned* __restrict__ Apk, const unsigned* __restrict__ Whi,
    const float* __restrict__ bias, float* __restrict__ C)
{
    __shared__ unsigned Ah[128 * GW];
    __shared__ unsigned Bh[128 * GW];

    const int tid  = threadIdx.x;
    const int lane = tid & 31;
    const int wid  = tid >> 5;
    const int wm   = wid >> 2;
    const int wn   = wid & 3;
    const int g    = lane >> 2;
    const int c    = lane & 3;
    const int bm   = blockIdx.x;
    const int bn   = blockIdx.y;

    const int lrow = tid >> 1;
    const int lkw  = (tid & 1) << 2;           // word offset 0 or 4
    const int wbase = lrow * GW + lkw;

    const unsigned* Ap  = Apk + (size_t)(bm * 128 + lrow) * (DMODEL / 2) + lkw;
    const unsigned* Whp = Whi + (size_t)(bn * 128 + lrow) * (DMODEL / 2) + lkw;

    float acc[4][4][4];
#pragma unroll
    for (int i = 0; i < 4; i++)
#pragma unroll
        for (int j = 0; j < 4; j++)
#pragma unroll
            for (int k = 0; k < 4; k++) acc[i][j][k] = 0.f;

    uint4 rAh = *(const uint4*)(Ap);
    uint4 rWh = *(const uint4*)(Whp);

    for (int k0 = 0; k0 < DMODEL; k0 += 16) {
        __syncthreads();
        *(uint4*)&Ah[wbase] = rAh;
        *(uint4*)&Bh[wbase] = rWh;
        __syncthreads();

        if (k0 + 16 < DMODEL) {
            rAh = *(const uint4*)(Ap + ((k0 + 16) >> 1));
            rWh = *(const uint4*)(Whp + ((k0 + 16) >> 1));
        }

        unsigned ah[4][4], bh[4][2];
#pragma unroll
        for (int ma = 0; ma < 4; ma++) {
            const int r  = wm * 64 + ma * 16 + g;
            const int b0 = r * GW + c;
            const int b1 = (r + 8) * GW + c;
            ah[ma][0] = Ah[b0]; ah[ma][1] = Ah[b1];
            ah[ma][2] = Ah[b0 + 4]; ah[ma][3] = Ah[b1 + 4];
        }
#pragma unroll
        for (int na = 0; na < 4; na++) {
            const int nb = (wn * 32 + na * 8 + g) * GW + c;
            bh[na][0] = Bh[nb]; bh[na][1] = Bh[nb + 4];
        }
#pragma unroll
        for (int ma = 0; ma < 4; ma++)
#pragma unroll
            for (int na = 0; na < 4; na++)
                mma16h(acc[ma][na], ah[ma], bh[na]);
    }

#pragma unroll
    for (int ma = 0; ma < 4; ma++) {
        const int m0 = bm * 128 + wm * 64 + ma * 16 + g;
#pragma unroll
        for (int na = 0; na < 4; na++) {
            const int n  = bn * 128 + wn * 32 + na * 8 + (c << 1);
            const float b0 = bias[n], b1 = bias[n + 1];
            *(float2*)&C[(size_t)m0 * DMODEL + n] =
                make_float2(acc[ma][na][0] + b0, acc[ma][na][1] + b1);
            *(float2*)&C[(size_t)(m0 + 8) * DMODEL + n] =
                make_float2(acc[ma][na][2] + b0, acc[ma][na][3] + b1);
        }
    }
}

// ---------------------------------------------------------------------------
// Flash attention, fp16 MMA + ldmatrix, 32 q-rows/warp,
// cp.async double-buffered pre-packed fp16 K/V tiles.
// grid = (16 qtiles of 128 rows, BH). 128 threads = 4 warps.
// smem (dynamic): Kbuf[2] 64xKW, Vbuf[2] 64xKW, Ps 128xKW  (words)
// ---------------------------------------------------------------------------
#define KW 36
#define KVW (64 * KW)                        /* words per K or V buffer */
#define ATTN_SMEM ((4 * KVW + 128 * KW) * 4) /* 55296 bytes */

__global__ __launch_bounds__(128) void attn_fp16_kernel(
    const unsigned* __restrict__ Qp, const unsigned* __restrict__ Kp,
    const unsigned* __restrict__ Vt, unsigned* __restrict__ OutP)
{
    extern __shared__ unsigned smem[];
    unsigned* Ps = smem + 4 * KVW;

    const int tid  = threadIdx.x;
    const int lane = tid & 31;
    const int w    = tid >> 5;
    const int g    = lane >> 2;
    const int c    = lane & 3;
    const int qtile = blockIdx.x;
    const int bh    = blockIdx.y;

    const unsigned sbase = smem_u32(smem);
    const unsigned kbase[2] = {sbase, sbase + KVW * 4u};
    const unsigned vbase[2] = {sbase + 2u * KVW * 4u, sbase + 3u * KVW * 4u};
    const unsigned ps_b = sbase + 4u * KVW * 4u;

    const unsigned off_b =
        ((unsigned)(((lane >> 4) * 8 + (lane & 7)) * KW + ((lane >> 3) & 1) * 4)) * 4u;
    const unsigned off_a =
        ((unsigned)((w * 32 + ((lane >> 3) & 1) * 8 + (lane & 7)) * KW
                    + (lane >> 4) * 4)) * 4u;

    // per-thread cp.async source/dest offsets (4 chunks each for K and V)
    const unsigned* Kt_b = Kp + ((size_t)bh * S_LEN) * 32;
    const unsigned* Vt_b = Vt + (size_t)bh * HDIM * (S_LEN / 2);

    // Q fragments direct from packed gmem (pre-scaled by 1/8 at projection)
    unsigned qa[2][4][4];
    {
        const unsigned* Qw = Qp + ((size_t)bh * S_LEN + qtile * 128 + w * 32) * 32;
#pragma unroll
        for (int mt = 0; mt < 2; mt++)
#pragma unroll
            for (int ks = 0; ks < 4; ks++) {
                qa[mt][ks][0] = Qw[(mt * 16 + g) * 32 + ks * 8 + c];
                qa[mt][ks][1] = Qw[(mt * 16 + g + 8) * 32 + ks * 8 + c];
                qa[mt][ks][2] = Qw[(mt * 16 + g) * 32 + ks * 8 + c + 4];
                qa[mt][ks][3] = Qw[(mt * 16 + g + 8) * 32 + ks * 8 + c + 4];
            }
    }

    float oacc[2][8][4];
#pragma unroll
    for (int mt = 0; mt < 2; mt++)
#pragma unroll
        for (int i = 0; i < 8; i++)
#pragma unroll
            for (int j = 0; j < 4; j++) oacc[mt][i][j] = 0.f;
    float mrow[4] = {-1e30f, -1e30f, -1e30f, -1e30f};
    float lrow[4] = {0.f, 0.f, 0.f, 0.f};

    const int NT = S_LEN / 64;

    // prologue: issue tile 0 into buffer 0
    {
#pragma unroll
        for (int i = 0; i < 4; i++) {
            const int f = tid + i * 128;            // 0..511
            const int row = f >> 3, ch = f & 7;
            cpa16(kbase[0] + (unsigned)(row * KW + ch * 4) * 4u,
                  Kt_b + (size_t)row * 32 + ch * 4);
            cpa16(vbase[0] + (unsigned)(row * KW + ch * 4) * 4u,
                  Vt_b + (size_t)row * (S_LEN / 2) + ch * 4);
        }
        cpa_commit();
    }

    for (int kt = 0; kt < NT; kt++) {
        const int cur = kt & 1;
        if (kt + 1 < NT) {
            const int nxt = cur ^ 1;
            const unsigned* Ksrc = Kt_b + (size_t)(kt + 1) * 64 * 32;
            const unsigned* Vsrc = Vt_b + (size_t)(kt + 1) * 32;
#pragma unroll
            for (int i = 0; i < 4; i++) {
                const int f = tid + i * 128;
                const int row = f >> 3, ch = f & 7;
                cpa16(kbase[nxt] + (unsigned)(row * KW + ch * 4) * 4u,
                      Ksrc + (size_t)row * 32 + ch * 4);
                cpa16(vbase[nxt] + (unsigned)(row * KW + ch * 4) * 4u,
                      Vsrc + (size_t)row * (S_LEN / 2) + ch * 4);
            }
            cpa_commit();
            cpa_wait1();
        } else {
            cpa_wait0();
        }
        __syncthreads();

        const unsigned ks_b = kbase[cur];
        const unsigned vs_b = vbase[cur];

        // ---- S = (Q/8) @ K^T ----
        float sacc[2][8][4];
#pragma unroll
        for (int mt = 0; mt < 2; mt++)
#pragma unroll
            for (int i = 0; i < 8; i++)
#pragma unroll
                for (int j = 0; j < 4; j++) sacc[mt][i][j] = 0.f;
#pragma unroll
        for (int ks = 0; ks < 4; ks++) {
#pragma unroll
            for (int p = 0; p < 4; p++) {
                unsigned kb[4];
                ldsm4(kb, ks_b + (unsigned)(p * 16 * KW + ks * 8) * 4u + off_b);
#pragma unroll
                for (int mt = 0; mt < 2; mt++) {
                    mma16h(sacc[mt][2 * p],     qa[mt][ks], kb);
                    mma16h(sacc[mt][2 * p + 1], qa[mt][ks], kb + 2);
                }
            }
        }

        // ---- online softmax (4 row groups) ----
        float tm[4] = {-1e30f, -1e30f, -1e30f, -1e30f};
#pragma unroll
        for (int mt = 0; mt < 2; mt++)
#pragma unroll
            for (int na = 0; na < 8; na++) {
                tm[2 * mt]     = fmaxf(tm[2 * mt],
                                       fmaxf(sacc[mt][na][0], sacc[mt][na][1]));
                tm[2 * mt + 1] = fmaxf(tm[2 * mt + 1],
                                       fmaxf(sacc[mt][na][2], sacc[mt][na][3]));
            }
        float mn[4], alpha[4];
#pragma unroll
        for (int rg = 0; rg < 4; rg++) {
            tm[rg] = fmaxf(tm[rg], __shfl_xor_sync(0xffffffffu, tm[rg], 1));
            tm[rg] = fmaxf(tm[rg], __shfl_xor_sync(0xffffffffu, tm[rg], 2));
            mn[rg] = fmaxf(mrow[rg], tm[rg]);
            alpha[rg] = __expf(mrow[rg] - mn[rg]);
            mrow[rg] = mn[rg];
        }

        float rs[4] = {0.f, 0.f, 0.f, 0.f};
#pragma unroll
        for (int mt = 0; mt < 2; mt++) {
            const int pr0 = (w * 32 + mt * 16 + g) * KW;
            const int pr1 = pr0 + 8 * KW;
#pragma unroll
            for (int na = 0; na < 8; na++) {
                const float p0 = __expf(sacc[mt][na][0] - mn[2 * mt]);
                const float p1 = __expf(sacc[mt][na][1] - mn[2 * mt]);
                const float p2 = __expf(sacc[mt][na][2] - mn[2 * mt + 1]);
                const float p3 = __expf(sacc[mt][na][3] - mn[2 * mt + 1]);
                rs[2 * mt]     += p0 + p1;
                rs[2 * mt + 1] += p2 + p3;
                Ps[pr0 + na * 4 + c] = hpack(p0, p1);
                Ps[pr1 + na * 4 + c] = hpack(p2, p3);
            }
        }
#pragma unroll
        for (int rg = 0; rg < 4; rg++) {
            rs[rg] += __shfl_xor_sync(0xffffffffu, rs[rg], 1);
            rs[rg] += __shfl_xor_sync(0xffffffffu, rs[rg], 2);
            lrow[rg] = lrow[rg] * alpha[rg] + rs[rg];
        }
#pragma unroll
        for (int mt = 0; mt < 2; mt++)
#pragma unroll
            for (int na = 0; na < 8; na++) {
                oacc[mt][na][0] *= alpha[2 * mt];
                oacc[mt][na][1] *= alpha[2 * mt];
                oacc[mt][na][2] *= alpha[2 * mt + 1];
                oacc[mt][na][3] *= alpha[2 * mt + 1];
            }
        __syncwarp();   // Ps rows are warp-private

        // ---- O += P @ V ----
#pragma unroll
        for (int ks = 0; ks < 4; ks++) {
            unsigned pa[2][4];
            ldsm4(pa[0], ps_b + (unsigned)(ks * 8) * 4u + off_a);
            ldsm4(pa[1], ps_b + (unsigned)(16 * KW + ks * 8) * 4u + off_a);
#pragma unroll
            for (int p = 0; p < 4; p++) {
                unsigned vb[4];
                ldsm4(vb, vs_b + (unsigned)(p * 16 * KW + ks * 8) * 4u + off_b);
#pragma unroll
                for (int mt = 0; mt < 2; mt++) {
                    mma16h(oacc[mt][2 * p],     pa[mt], vb);
                    mma16h(oacc[mt][2 * p + 1], pa[mt], vb + 2);
                }
            }
        }
        __syncthreads();   // compute done before buffer reuse next iter
    }

    // ---- epilogue: packed fp16 words for the O projection ----
    const int b = bh >> 4, h = bh & 15;
#pragma unroll
    for (int mt = 0; mt < 2; mt++) {
        const float inv0 = 1.f / lrow[2 * mt];
        const float inv1 = 1.f / lrow[2 * mt + 1];
        const int s0 = qtile * 128 + w * 32 + mt * 16 + g;
        unsigned* o0 = OutP + ((size_t)(b * S_LEN + s0)) * (DMODEL / 2) + h * 32;
        unsigned* o1 = o0 + (size_t)8 * (DMODEL / 2);
#pragma unroll
        for (int na = 0; na < 8; na++) {
            o0[na * 4 + c] = hpack(oacc[mt][na][0] * inv0, oacc[mt][na][1] * inv0);
            o1[na * 4 + c] = hpack(oacc[mt][na][2] * inv1, oacc[mt][na][3] * inv1);
        }
    }
}

// ---------------------------------------------------------------------------
extern "C" void kernel_launch(void* const* d_in, const int* in_sizes, int n_in,
                              void* d_out, int out_size)
{
    const float* query = (const float*)d_in[0];
    const float* key   = (const float*)d_in[1];
    const float* value = (const float*)d_in[2];
    const float* Wq = (const float*)d_in[3];
    const float* bq = (const float*)d_in[4];
    const float* Wk = (const float*)d_in[5];
    const float* bk = (const float*)d_in[6];
    const float* Wv = (const float*)d_in[7];
    const float* bv = (const float*)d_in[8];
    const float* Wo = (const float*)d_in[9];
    const float* bo = (const float*)d_in[10];
    float* out = (float*)d_out;

    unsigned *pQp, *pKp, *pVp, *pVt, *pAp, *pWh;
    cudaGetSymbolAddress((void**)&pQp, g_Qp);
    cudaGetSymbolAddress((void**)&pKp, g_Kp);
    cudaGetSymbolAddress((void**)&pVp, g_Vp);
    cudaGetSymbolAddress((void**)&pVt, g_Vt);
    cudaGetSymbolAddress((void**)&pAp, g_attnP);
    cudaGetSymbolAddress((void**)&pWh, g_Wh);

    static int smem_set = 0;
    if (!smem_set) {
        cudaFuncSetAttribute(attn_fp16_kernel,
                             cudaFuncAttributeMaxDynamicSharedMemorySize,
                             ATTN_SMEM);
        smem_set = 1;
    }

    // pack all four weight matrices in one launch
    dim3 pgrid(WPK / 256, 4);
    pack_w_kernel<<<pgrid, 256>>>(Wq, Wk, Wv, Wo, pWh);

    dim3 ggrid(M_ROWS / 128, DMODEL / 128);
    gemm_fp16_kernel<<<ggrid, 256>>>(query, pWh + 0 * (size_t)WPK, bq, pQp, 1, 0.125f);
    gemm_fp16_kernel<<<ggrid, 256>>>(key,   pWh + 1 * (size_t)WPK, bk, pKp, 1, 1.0f);
    gemm_fp16_kernel<<<ggrid, 256>>>(value, pWh + 2 * (size_t)WPK, bv, pVp, 1, 1.0f);

    dim3 vgrid(S_LEN / 64, BH);
    vtrans_kernel<<<vgrid, 256>>>(pVp, pVt);

    dim3 agrid(S_LEN / 128, BH);
    attn_fp16_kernel<<<agrid, 128, ATTN_SMEM>>>(pQp, pKp, pVt, pAp);

    gemm_fp16_pA_kernel<<<ggrid, 256>>>(pAp, pWh + 3 * (size_t)WPK, bo, out);
}

// round 10
// speedup vs baseline: 2.3186x; 1.1372x over previous
#include <cuda_runtime.h>
#include <cuda_fp16.h>

#define S_LEN   2048
#define DMODEL  1024
#define NHEAD   16
#define HDIM    64
#define BATCH   2
#define M_ROWS  (BATCH * S_LEN)   /* 4096 */
#define BH      (BATCH * NHEAD)   /* 32 */

// Scratch (allocation-free rule: __device__ globals).
// Packed fp16 word layouts (one unsigned = 2 fp16):
#define APK (M_ROWS * (DMODEL / 2))          /* words per packed input */
__device__ unsigned g_Inp[3 * APK];          /* packed query/key/value */
__device__ unsigned g_Qp[BH * S_LEN * (HDIM / 2)];
__device__ unsigned g_Kp[BH * S_LEN * (HDIM / 2)];
__device__ unsigned g_Vp[BH * S_LEN * (HDIM / 2)];
__device__ unsigned g_Vt[BH * HDIM * (S_LEN / 2)];
__device__ unsigned g_attnP[M_ROWS * (DMODEL / 2)];
#define WPK (DMODEL * (DMODEL / 2))
__device__ unsigned g_Wh[4 * WPK];

// ---------------------------------------------------------------------------
// helpers
// ---------------------------------------------------------------------------
__device__ __forceinline__ void mma16h(float* d, const unsigned* a, const unsigned* b) {
    asm volatile(
        "mma.sync.aligned.m16n8k16.row.col.f32.f16.f16.f32 "
        "{%0,%1,%2,%3}, {%4,%5,%6,%7}, {%8,%9}, {%0,%1,%2,%3};\n"
        : "+f"(d[0]), "+f"(d[1]), "+f"(d[2]), "+f"(d[3])
        : "r"(a[0]), "r"(a[1]), "r"(a[2]), "r"(a[3]), "r"(b[0]), "r"(b[1]));
}

__device__ __forceinline__ void ldsm4(unsigned* r, unsigned addr) {
    asm volatile(
        "ldmatrix.sync.aligned.m8n8.x4.shared.b16 {%0,%1,%2,%3}, [%4];"
        : "=r"(r[0]), "=r"(r[1]), "=r"(r[2]), "=r"(r[3]) : "r"(addr));
}

__device__ __forceinline__ unsigned hpack(float lo_k, float hi_k) {
    __half2 t = __floats2half2_rn(lo_k, hi_k);             // .x = even k (low)
    return *(unsigned*)&t;
}

__device__ __forceinline__ unsigned smem_u32(const void* p) {
    return (unsigned)__cvta_generic_to_shared(p);
}

__device__ __forceinline__ void cpa16(unsigned dst, const void* src) {
    asm volatile("cp.async.cg.shared.global [%0], [%1], 16;\n"
                 :: "r"(dst), "l"(src));
}
__device__ __forceinline__ void cpa_commit() {
    asm volatile("cp.async.commit_group;\n");
}
__device__ __forceinline__ void cpa_wait1() {
    asm volatile("cp.async.wait_group 1;\n");
}
__device__ __forceinline__ void cpa_wait0() {
    asm volatile("cp.async.wait_group 0;\n");
}

// ---------------------------------------------------------------------------
// packers: fp32 -> fp16 k-pair words
// ---------------------------------------------------------------------------
__global__ __launch_bounds__(256) void pack_w_kernel(
    const float* __restrict__ W0, const float* __restrict__ W1,
    const float* __restrict__ W2, const float* __restrict__ W3,
    unsigned* __restrict__ Wh)
{
    const int by = blockIdx.y;
    const float* W = (by == 0) ? W0 : (by == 1) ? W1 : (by == 2) ? W2 : W3;
    const int i = blockIdx.x * 256 + threadIdx.x;
    float2 v = *(const float2*)(W + (size_t)i * 2);
    Wh[(size_t)by * WPK + i] = hpack(v.x, v.y);
}

__global__ __launch_bounds__(256) void pack_in_kernel(
    const float* __restrict__ q, const float* __restrict__ k,
    const float* __restrict__ v, unsigned* __restrict__ dst)
{
    const int by = blockIdx.y;
    const float* src = (by == 0) ? q : (by == 1) ? k : v;
    const size_t i = (size_t)blockIdx.x * 256 + threadIdx.x;
    float2 val = *(const float2*)(src + i * 2);
    dst[(size_t)by * APK + i] = hpack(val.x, val.y);
}

// ---------------------------------------------------------------------------
// V transpose-pack: g_Vp [bh][key][32 d-words] -> g_Vt [bh][d][key-pair words]
// ---------------------------------------------------------------------------
__global__ __launch_bounds__(256) void vtrans_kernel(
    const unsigned* __restrict__ Vp, unsigned* __restrict__ Vt)
{
    __shared__ unsigned sT[64 * 33];
    const int t  = threadIdx.x;
    const int kt = blockIdx.x;
    const int bh = blockIdx.y;

    const unsigned* src = Vp + ((size_t)bh * S_LEN + kt * 64) * (HDIM / 2);
#pragma unroll
    for (int i = 0; i < 8; i++) {
        const int idx = t + i * 256;
        sT[(idx >> 5) * 33 + (idx & 31)] = src[idx];
    }
    __syncthreads();

    unsigned* dst = Vt + (size_t)bh * HDIM * (S_LEN / 2) + kt * 32;
#pragma unroll
    for (int i = 0; i < 8; i++) {
        const int idx = t + i * 256;
        const int kp = idx & 31;
        const int d  = idx >> 5;
        const unsigned w0 = sT[(2 * kp) * 33 + (d >> 1)];
        const unsigned w1 = sT[(2 * kp + 1) * 33 + (d >> 1)];
        dst[(size_t)d * (S_LEN / 2) + kp] =
            __byte_perm(w0, w1, (d & 1) ? 0x7632 : 0x5410);
    }
}

// ---------------------------------------------------------------------------
// Pipelined fp16 GEMM on packed A/W:  C[m,n] = sum_k A[m,k]*W[n,k] + bias[n]
// CTA 128x128, BK=32, 3-stage cp.async ring, ONE __syncthreads per iter.
// 256 threads, 8 warps (2Mx4N, warp tile 64x32).
// mode 1: headsplit packed fp16 out (*scale); mode 0: flat fp32 out.
// ---------------------------------------------------------------------------
#define GST 20   /* row stride words: 16 data + 4 pad (conflict-free) */
#define GSTAGE (2 * 128 * GST)            /* words per stage (A then B) */
#define GEMM_SMEM (3 * GSTAGE * 4)        /* 61440 bytes */

__global__ __launch_bounds__(256) void gemm_pk_kernel(
    const unsigned* __restrict__ Apk, const unsigned* __restrict__ Whi,
    const float* __restrict__ bias, void* __restrict__ Cv,
    int mode, float scale)
{
    extern __shared__ unsigned gs[];

    const int tid  = threadIdx.x;
    const int lane = tid & 31;
    const int wid  = tid >> 5;
    const int wm   = wid >> 2;
    const int wn   = wid & 3;
    const int g    = lane >> 2;
    const int c    = lane & 3;
    const int bm   = blockIdx.x;
    const int bn   = blockIdx.y;

    const unsigned sbase = smem_u32(gs);
    const int crow = tid >> 2;                 // 0..63 base row for copies
    const int cchw = (tid & 3) << 2;           // word offset 0/4/8/12

    const unsigned* Aglob = Apk + (size_t)(bm * 128) * (DMODEL / 2);
    const unsigned* Bglob = Whi + (size_t)(bn * 128) * (DMODEL / 2);

    float acc[4][4][4];
#pragma unroll
    for (int i = 0; i < 4; i++)
#pragma unroll
        for (int j = 0; j < 4; j++)
#pragma unroll
            for (int k = 0; k < 4; k++) acc[i][j][k] = 0.f;

    // issue one stage's copies (A: 512 chunks, B: 512 chunks; 2 each/thread)
    auto issue = [&](int stage, int k0w) {
        const unsigned ab = sbase + (unsigned)(stage * GSTAGE) * 4u;
        const unsigned bb = ab + (unsigned)(128 * GST) * 4u;
#pragma unroll
        for (int i = 0; i < 2; i++) {
            const int row = crow + i * 64;
            cpa16(ab + (unsigned)(row * GST + cchw) * 4u,
                  Aglob + (size_t)row * (DMODEL / 2) + k0w + cchw);
            cpa16(bb + (unsigned)(row * GST + cchw) * 4u,
                  Bglob + (size_t)row * (DMODEL / 2) + k0w + cchw);
        }
        cpa_commit();
    };

    issue(0, 0);
    issue(1, 16);

    const int NIT = DMODEL / 32;   // 32
    for (int it = 0; it < NIT; it++) {
        const int cur = it % 3;
        if (it == NIT - 1) cpa_wait0(); else cpa_wait1();
        __syncthreads();           // also: all warps done reading stage (it+2)%3

        if (it + 2 < NIT) issue((it + 2) % 3, (it + 2) * 16);

        const unsigned ab = sbase + (unsigned)(cur * GSTAGE) * 4u;
        const unsigned bb = ab + (unsigned)(128 * GST) * 4u;
        unsigned* Ac = gs + cur * GSTAGE;
        unsigned* Bc = Ac + 128 * GST;
        (void)ab; (void)bb;

#pragma unroll
        for (int s = 0; s < 2; s++) {
            const int s8 = s * 8;
            unsigned ah[4][4], bh[4][2];
#pragma unroll
            for (int ma = 0; ma < 4; ma++) {
                const int r  = wm * 64 + ma * 16 + g;
                const int b0 = r * GST + s8 + c;
                const int b1 = (r + 8) * GST + s8 + c;
                ah[ma][0] = Ac[b0]; ah[ma][1] = Ac[b1];
                ah[ma][2] = Ac[b0 + 4]; ah[ma][3] = Ac[b1 + 4];
            }
#pragma unroll
            for (int na = 0; na < 4; na++) {
                const int nb = (wn * 32 + na * 8 + g) * GST + s8 + c;
                bh[na][0] = Bc[nb]; bh[na][1] = Bc[nb + 4];
            }
#pragma unroll
            for (int ma = 0; ma < 4; ma++)
#pragma unroll
                for (int na = 0; na < 4; na++)
                    mma16h(acc[ma][na], ah[ma], bh[na]);
        }
    }

    // epilogue
#pragma unroll
    for (int ma = 0; ma < 4; ma++) {
        const int m0 = bm * 128 + wm * 64 + ma * 16 + g;
#pragma unroll
        for (int na = 0; na < 4; na++) {
            const int n  = bn * 128 + wn * 32 + na * 8 + (c << 1);
            const float b0 = bias[n], b1 = bias[n + 1];
            const float v00 = acc[ma][na][0] + b0, v01 = acc[ma][na][1] + b1;
            const float v10 = acc[ma][na][2] + b0, v11 = acc[ma][na][3] + b1;
            if (mode) {
                unsigned* Cp = (unsigned*)Cv;
                const int h = n >> 6, dw = (n & 63) >> 1;
                const int b_0 = m0 >> 11, s_0 = m0 & (S_LEN - 1);
                const int b_1 = (m0 + 8) >> 11, s_1 = (m0 + 8) & (S_LEN - 1);
                Cp[((size_t)((b_0 * NHEAD + h) * S_LEN + s_0)) * 32 + dw] =
                    hpack(scale * v00, scale * v01);
                Cp[((size_t)((b_1 * NHEAD + h) * S_LEN + s_1)) * 32 + dw] =
                    hpack(scale * v10, scale * v11);
            } else {
                float* C = (float*)Cv;
                *(float2*)&C[(size_t)m0 * DMODEL + n]       = make_float2(v00, v01);
                *(float2*)&C[(size_t)(m0 + 8) * DMODEL + n] = make_float2(v10, v11);
            }
        }
    }
}

// ---------------------------------------------------------------------------
// Flash attention, fp16 MMA + ldmatrix, 32 q-rows/warp,
// cp.async double-buffered pre-packed fp16 K/V tiles. (unchanged, round-8)
// ---------------------------------------------------------------------------
#define KW 36
#define KVW (64 * KW)
#define ATTN_SMEM ((4 * KVW + 128 * KW) * 4)

__global__ __launch_bounds__(128) void attn_fp16_kernel(
    const unsigned* __restrict__ Qp, const unsigned* __restrict__ Kp,
    const unsigned* __restrict__ Vt, unsigned* __restrict__ OutP)
{
    extern __shared__ unsigned smem[];
    unsigned* Ps = smem + 4 * KVW;

    const int tid  = threadIdx.x;
    const int lane = tid & 31;
    const int w    = tid >> 5;
    const int g    = lane >> 2;
    const int c    = lane & 3;
    const int qtile = blockIdx.x;
    const int bh    = blockIdx.y;

    const unsigned sbase = smem_u32(smem);
    const unsigned kbase[2] = {sbase, sbase + KVW * 4u};
    const unsigned vbase[2] = {sbase + 2u * KVW * 4u, sbase + 3u * KVW * 4u};
    const unsigned ps_b = sbase + 4u * KVW * 4u;

    const unsigned off_b =
        ((unsigned)(((lane >> 4) * 8 + (lane & 7)) * KW + ((lane >> 3) & 1) * 4)) * 4u;
    const unsigned off_a =
        ((unsigned)((w * 32 + ((lane >> 3) & 1) * 8 + (lane & 7)) * KW
                    + (lane >> 4) * 4)) * 4u;

    const unsigned* Kt_b = Kp + ((size_t)bh * S_LEN) * 32;
    const unsigned* Vt_b = Vt + (size_t)bh * HDIM * (S_LEN / 2);

    unsigned qa[2][4][4];
    {
        const unsigned* Qw = Qp + ((size_t)bh * S_LEN + qtile * 128 + w * 32) * 32;
#pragma unroll
        for (int mt = 0; mt < 2; mt++)
#pragma unroll
            for (int ks = 0; ks < 4; ks++) {
                qa[mt][ks][0] = Qw[(mt * 16 + g) * 32 + ks * 8 + c];
                qa[mt][ks][1] = Qw[(mt * 16 + g + 8) * 32 + ks * 8 + c];
                qa[mt][ks][2] = Qw[(mt * 16 + g) * 32 + ks * 8 + c + 4];
                qa[mt][ks][3] = Qw[(mt * 16 + g + 8) * 32 + ks * 8 + c + 4];
            }
    }

    float oacc[2][8][4];
#pragma unroll
    for (int mt = 0; mt < 2; mt++)
#pragma unroll
        for (int i = 0; i < 8; i++)
#pragma unroll
            for (int j = 0; j < 4; j++) oacc[mt][i][j] = 0.f;
    float mrow[4] = {-1e30f, -1e30f, -1e30f, -1e30f};
    float lrow[4] = {0.f, 0.f, 0.f, 0.f};

    const int NT = S_LEN / 64;

    {
#pragma unroll
        for (int i = 0; i < 4; i++) {
            const int f = tid + i * 128;
            const int row = f >> 3, ch = f & 7;
            cpa16(kbase[0] + (unsigned)(row * KW + ch * 4) * 4u,
                  Kt_b + (size_t)row * 32 + ch * 4);
            cpa16(vbase[0] + (unsigned)(row * KW + ch * 4) * 4u,
                  Vt_b + (size_t)row * (S_LEN / 2) + ch * 4);
        }
        cpa_commit();
    }

    for (int kt = 0; kt < NT; kt++) {
        const int cur = kt & 1;
        if (kt + 1 < NT) {
            const int nxt = cur ^ 1;
            const unsigned* Ksrc = Kt_b + (size_t)(kt + 1) * 64 * 32;
            const unsigned* Vsrc = Vt_b + (size_t)(kt + 1) * 32;
#pragma unroll
            for (int i = 0; i < 4; i++) {
                const int f = tid + i * 128;
                const int row = f >> 3, ch = f & 7;
                cpa16(kbase[nxt] + (unsigned)(row * KW + ch * 4) * 4u,
                      Ksrc + (size_t)row * 32 + ch * 4);
                cpa16(vbase[nxt] + (unsigned)(row * KW + ch * 4) * 4u,
                      Vsrc + (size_t)row * (S_LEN / 2) + ch * 4);
            }
            cpa_commit();
            cpa_wait1();
        } else {
            cpa_wait0();
        }
        __syncthreads();

        const unsigned ks_b = kbase[cur];
        const unsigned vs_b = vbase[cur];

        float sacc[2][8][4];
#pragma unroll
        for (int mt = 0; mt < 2; mt++)
#pragma unroll
            for (int i = 0; i < 8; i++)
#pragma unroll
                for (int j = 0; j < 4; j++) sacc[mt][i][j] = 0.f;
#pragma unroll
        for (int ks = 0; ks < 4; ks++) {
#pragma unroll
            for (int p = 0; p < 4; p++) {
                unsigned kb[4];
                ldsm4(kb, ks_b + (unsigned)(p * 16 * KW + ks * 8) * 4u + off_b);
#pragma unroll
                for (int mt = 0; mt < 2; mt++) {
                    mma16h(sacc[mt][2 * p],     qa[mt][ks], kb);
                    mma16h(sacc[mt][2 * p + 1], qa[mt][ks], kb + 2);
                }
            }
        }

        float tm[4] = {-1e30f, -1e30f, -1e30f, -1e30f};
#pragma unroll
        for (int mt = 0; mt < 2; mt++)
#pragma unroll
            for (int na = 0; na < 8; na++) {
                tm[2 * mt]     = fmaxf(tm[2 * mt],
                                       fmaxf(sacc[mt][na][0], sacc[mt][na][1]));
                tm[2 * mt + 1] = fmaxf(tm[2 * mt + 1],
                                       fmaxf(sacc[mt][na][2], sacc[mt][na][3]));
            }
        float mn[4], alpha[4];
#pragma unroll
        for (int rg = 0; rg < 4; rg++) {
            tm[rg] = fmaxf(tm[rg], __shfl_xor_sync(0xffffffffu, tm[rg], 1));
            tm[rg] = fmaxf(tm[rg], __shfl_xor_sync(0xffffffffu, tm[rg], 2));
            mn[rg] = fmaxf(mrow[rg], tm[rg]);
            alpha[rg] = __expf(mrow[rg] - mn[rg]);
            mrow[rg] = mn[rg];
        }

        float rs[4] = {0.f, 0.f, 0.f, 0.f};
#pragma unroll
        for (int mt = 0; mt < 2; mt++) {
            const int pr0 = (w * 32 + mt * 16 + g) * KW;
            const int pr1 = pr0 + 8 * KW;
#pragma unroll
            for (int na = 0; na < 8; na++) {
                const float p0 = __expf(sacc[mt][na][0] - mn[2 * mt]);
                const float p1 = __expf(sacc[mt][na][1] - mn[2 * mt]);
                const float p2 = __expf(sacc[mt][na][2] - mn[2 * mt + 1]);
                const float p3 = __expf(sacc[mt][na][3] - mn[2 * mt + 1]);
                rs[2 * mt]     += p0 + p1;
                rs[2 * mt + 1] += p2 + p3;
                Ps[pr0 + na * 4 + c] = hpack(p0, p1);
                Ps[pr1 + na * 4 + c] = hpack(p2, p3);
            }
        }
#pragma unroll
        for (int rg = 0; rg < 4; rg++) {
            rs[rg] += __shfl_xor_sync(0xffffffffu, rs[rg], 1);
            rs[rg] += __shfl_xor_sync(0xffffffffu, rs[rg], 2);
            lrow[rg] = lrow[rg] * alpha[rg] + rs[rg];
        }
#pragma unroll
        for (int mt = 0; mt < 2; mt++)
#pragma unroll
            for (int na = 0; na < 8; na++) {
                oacc[mt][na][0] *= alpha[2 * mt];
                oacc[mt][na][1] *= alpha[2 * mt];
                oacc[mt][na][2] *= alpha[2 * mt + 1];
                oacc[mt][na][3] *= alpha[2 * mt + 1];
            }
        __syncwarp();

#pragma unroll
        for (int ks = 0; ks < 4; ks++) {
            unsigned pa[2][4];
            ldsm4(pa[0], ps_b + (unsigned)(ks * 8) * 4u + off_a);
            ldsm4(pa[1], ps_b + (unsigned)(16 * KW + ks * 8) * 4u + off_a);
#pragma unroll
            for (int p = 0; p < 4; p++) {
                unsigned vb[4];
                ldsm4(vb, vs_b + (unsigned)(p * 16 * KW + ks * 8) * 4u + off_b);
#pragma unroll
                for (int mt = 0; mt < 2; mt++) {
                    mma16h(oacc[mt][2 * p],     pa[mt], vb);
                    mma16h(oacc[mt][2 * p + 1], pa[mt], vb + 2);
                }
            }
        }
        __syncthreads();
    }

    const int b = bh >> 4, h = bh & 15;
#pragma unroll
    for (int mt = 0; mt < 2; mt++) {
        const float inv0 = 1.f / lrow[2 * mt];
        const float inv1 = 1.f / lrow[2 * mt + 1];
        const int s0 = qtile * 128 + w * 32 + mt * 16 + g;
        unsigned* o0 = OutP + ((size_t)(b * S_LEN + s0)) * (DMODEL / 2) + h * 32;
        unsigned* o1 = o0 + (size_t)8 * (DMODEL / 2);
#pragma unroll
        for (int na = 0; na < 8; na++) {
            o0[na * 4 + c] = hpack(oacc[mt][na][0] * inv0, oacc[mt][na][1] * inv0);
            o1[na * 4 + c] = hpack(oacc[mt][na][2] * inv1, oacc[mt][na][3] * inv1);
        }
    }
}

// ---------------------------------------------------------------------------
extern "C" void kernel_launch(void* const* d_in, const int* in_sizes, int n_in,
                              void* d_out, int out_size)
{
    const float* query = (const float*)d_in[0];
    const float* key   = (const float*)d_in[1];
    const float* value = (const float*)d_in[2];
    const float* Wq = (const float*)d_in[3];
    const float* bq = (const float*)d_in[4];
    const float* Wk = (const float*)d_in[5];
    const float* bk = (const float*)d_in[6];
    const float* Wv = (const float*)d_in[7];
    const float* bv = (const float*)d_in[8];
    const float* Wo = (const float*)d_in[9];
    const float* bo = (const float*)d_in[10];
    float* out = (float*)d_out;

    unsigned *pIn, *pQp, *pKp, *pVp, *pVt, *pAp, *pWh;
    cudaGetSymbolAddress((void**)&pIn, g_Inp);
    cudaGetSymbolAddress((void**)&pQp, g_Qp);
    cudaGetSymbolAddress((void**)&pKp, g_Kp);
    cudaGetSymbolAddress((void**)&pVp, g_Vp);
    cudaGetSymbolAddress((void**)&pVt, g_Vt);
    cudaGetSymbolAddress((void**)&pAp, g_attnP);
    cudaGetSymbolAddress((void**)&pWh, g_Wh);

    static int smem_set = 0;
    if (!smem_set) {
        cudaFuncSetAttribute(attn_fp16_kernel,
                             cudaFuncAttributeMaxDynamicSharedMemorySize,
                             ATTN_SMEM);
        cudaFuncSetAttribute(gemm_pk_kernel,
                             cudaFuncAttributeMaxDynamicSharedMemorySize,
                             GEMM_SMEM);
        smem_set = 1;
    }

    dim3 pwgrid(WPK / 256, 4);
    pack_w_kernel<<<pwgrid, 256>>>(Wq, Wk, Wv, Wo, pWh);
    dim3 pigrid(APK / 256, 3);
    pack_in_kernel<<<pigrid, 256>>>(query, key, value, pIn);

    dim3 ggrid(M_ROWS / 128, DMODEL / 128);
    gemm_pk_kernel<<<ggrid, 256, GEMM_SMEM>>>(
        pIn + 0 * (size_t)APK, pWh + 0 * (size_t)WPK, bq, pQp, 1, 0.125f);
    gemm_pk_kernel<<<ggrid, 256, GEMM_SMEM>>>(
        pIn + 1 * (size_t)APK, pWh + 1 * (size_t)WPK, bk, pKp, 1, 1.0f);
    gemm_pk_kernel<<<ggrid, 256, GEMM_SMEM>>>(
        pIn + 2 * (size_t)APK, pWh + 2 * (size_t)WPK, bv, pVp, 1, 1.0f);

    dim3 vgrid(S_LEN / 64, BH);
    vtrans_kernel<<<vgrid, 256>>>(pVp, pVt);

    dim3 agrid(S_LEN / 128, BH);
    attn_fp16_kernel<<<agrid, 128, ATTN_SMEM>>>(pQp, pKp, pVt, pAp);

    gemm_pk_kernel<<<ggrid, 256, GEMM_SMEM>>>(
        pAp, pWh + 3 * (size_t)WPK, bo, out, 0, 1.0f);
}

// round 11
// speedup vs baseline: 2.4251x; 1.0460x over previous
#include <cuda_runtime.h>
#include <cuda_fp16.h>

#define S_LEN   2048
#define DMODEL  1024
#define NHEAD   16
#define HDIM    64
#define BATCH   2
#define M_ROWS  (BATCH * S_LEN)   /* 4096 */
#define BH      (BATCH * NHEAD)   /* 32 */

// Scratch (allocation-free rule: __device__ globals).
#define APK (M_ROWS * (DMODEL / 2))          /* words per packed 4096x1024 */
#define QKVC (BH * S_LEN * (HDIM / 2))       /* == APK */
__device__ unsigned g_Inp[3 * APK];          /* packed query/key/value */
__device__ unsigned g_QKVp[3 * QKVC];        /* packed Q,K,V headsplit */
__device__ unsigned g_Vt[BH * HDIM * (S_LEN / 2)];
__device__ unsigned g_attnP[M_ROWS * (DMODEL / 2)];
#define WPK (DMODEL * (DMODEL / 2))
__device__ unsigned g_Wh[4 * WPK];

// ---------------------------------------------------------------------------
// helpers
// ---------------------------------------------------------------------------
__device__ __forceinline__ void mma16h(float* d, const unsigned* a, const unsigned* b) {
    asm volatile(
        "mma.sync.aligned.m16n8k16.row.col.f32.f16.f16.f32 "
        "{%0,%1,%2,%3}, {%4,%5,%6,%7}, {%8,%9}, {%0,%1,%2,%3};\n"
        : "+f"(d[0]), "+f"(d[1]), "+f"(d[2]), "+f"(d[3])
        : "r"(a[0]), "r"(a[1]), "r"(a[2]), "r"(a[3]), "r"(b[0]), "r"(b[1]));
}

__device__ __forceinline__ void ldsm4(unsigned* r, unsigned addr) {
    asm volatile(
        "ldmatrix.sync.aligned.m8n8.x4.shared.b16 {%0,%1,%2,%3}, [%4];"
        : "=r"(r[0]), "=r"(r[1]), "=r"(r[2]), "=r"(r[3]) : "r"(addr));
}

__device__ __forceinline__ unsigned hpack(float lo_k, float hi_k) {
    __half2 t = __floats2half2_rn(lo_k, hi_k);             // .x = even k (low)
    return *(unsigned*)&t;
}

__device__ __forceinline__ unsigned smem_u32(const void* p) {
    return (unsigned)__cvta_generic_to_shared(p);
}

__device__ __forceinline__ void cpa16(unsigned dst, const void* src) {
    asm volatile("cp.async.cg.shared.global [%0], [%1], 16;\n"
                 :: "r"(dst), "l"(src));
}
__device__ __forceinline__ void cpa_commit() {
    asm volatile("cp.async.commit_group;\n");
}
__device__ __forceinline__ void cpa_wait1() {
    asm volatile("cp.async.wait_group 1;\n");
}
__device__ __forceinline__ void cpa_wait0() {
    asm volatile("cp.async.wait_group 0;\n");
}

// ---------------------------------------------------------------------------
// packers: fp32 -> fp16 k-pair words
// ---------------------------------------------------------------------------
__global__ __launch_bounds__(256) void pack_w_kernel(
    const float* __restrict__ W0, const float* __restrict__ W1,
    const float* __restrict__ W2, const float* __restrict__ W3,
    unsigned* __restrict__ Wh)
{
    const int by = blockIdx.y;
    const float* W = (by == 0) ? W0 : (by == 1) ? W1 : (by == 2) ? W2 : W3;
    const int i = blockIdx.x * 256 + threadIdx.x;
    float2 v = *(const float2*)(W + (size_t)i * 2);
    Wh[(size_t)by * WPK + i] = hpack(v.x, v.y);
}

__global__ __launch_bounds__(256) void pack_in_kernel(
    const float* __restrict__ q, const float* __restrict__ k,
    const float* __restrict__ v, unsigned* __restrict__ dst)
{
    const int by = blockIdx.y;
    const float* src = (by == 0) ? q : (by == 1) ? k : v;
    const size_t i = (size_t)blockIdx.x * 256 + threadIdx.x;
    float2 val = *(const float2*)(src + i * 2);
    dst[(size_t)by * APK + i] = hpack(val.x, val.y);
}

// ---------------------------------------------------------------------------
// V transpose-pack: Vp [bh][key][32 d-words] -> Vt [bh][d][key-pair words]
// ---------------------------------------------------------------------------
__global__ __launch_bounds__(256) void vtrans_kernel(
    const unsigned* __restrict__ Vp, unsigned* __restrict__ Vt)
{
    __shared__ unsigned sT[64 * 33];
    const int t  = threadIdx.x;
    const int kt = blockIdx.x;
    const int bh = blockIdx.y;

    const unsigned* src = Vp + ((size_t)bh * S_LEN + kt * 64) * (HDIM / 2);
#pragma unroll
    for (int i = 0; i < 8; i++) {
        const int idx = t + i * 256;
        sT[(idx >> 5) * 33 + (idx & 31)] = src[idx];
    }
    __syncthreads();

    unsigned* dst = Vt + (size_t)bh * HDIM * (S_LEN / 2) + kt * 32;
#pragma unroll
    for (int i = 0; i < 8; i++) {
        const int idx = t + i * 256;
        const int kp = idx & 31;
        const int d  = idx >> 5;
        const unsigned w0 = sT[(2 * kp) * 33 + (d >> 1)];
        const unsigned w1 = sT[(2 * kp + 1) * 33 + (d >> 1)];
        dst[(size_t)d * (S_LEN / 2) + kp] =
            __byte_perm(w0, w1, (d & 1) ? 0x7632 : 0x5410);
    }
}

// ---------------------------------------------------------------------------
// Pipelined fp16 GEMM, ldmatrix fragments, 3-stage cp.async ring.
// CTA 128x128, BK=32, 256 threads (8 warps, 2Mx4N).
// blockIdx.z selects input/weight/bias/output (fused QKV projections).
// mode 1: headsplit packed fp16 out (*scale for z==0); mode 0: flat fp32.
// ---------------------------------------------------------------------------
#define GST 20   /* row stride words: 16 data + 4 pad (ldsm conflict-free) */
#define GSTAGE (2 * 128 * GST)
#define GEMM_SMEM (3 * GSTAGE * 4)        /* 61440 bytes */

__global__ __launch_bounds__(256) void gemm_pk_kernel(
    const unsigned* __restrict__ Abase, const unsigned* __restrict__ Wbase,
    const float* __restrict__ b0p, const float* __restrict__ b1p,
    const float* __restrict__ b2p, void* __restrict__ Cv,
    int mode, float scale0)
{
    extern __shared__ unsigned gs[];

    const int tid  = threadIdx.x;
    const int lane = tid & 31;
    const int wid  = tid >> 5;
    const int wm   = wid >> 2;
    const int wn   = wid & 3;
    const int g    = lane >> 2;
    const int c    = lane & 3;
    const int bm   = blockIdx.x;
    const int bn   = blockIdx.y;
    const int z    = blockIdx.z;

    const float* bias = (z == 0) ? b0p : (z == 1) ? b1p : b2p;
    const float scale = (z == 0) ? scale0 : 1.0f;

    const unsigned sbase = smem_u32(gs);
    const int crow = tid >> 2;
    const int cchw = (tid & 3) << 2;

    const unsigned* Aglob = Abase + (size_t)z * APK + (size_t)(bm * 128) * (DMODEL / 2);
    const unsigned* Bglob = Wbase + (size_t)z * WPK + (size_t)(bn * 128) * (DMODEL / 2);

    // ldmatrix lane offsets (bytes)
    const unsigned a_off =
        ((unsigned)((wm * 64 + ((lane >> 3) & 1) * 8 + (lane & 7)) * GST
                    + (lane >> 4) * 4)) * 4u;
    const unsigned b_off =
        ((unsigned)((wn * 32 + (lane >> 4) * 8 + (lane & 7)) * GST
                    + ((lane >> 3) & 1) * 4)) * 4u;

    float acc[4][4][4];
#pragma unroll
    for (int i = 0; i < 4; i++)
#pragma unroll
        for (int j = 0; j < 4; j++)
#pragma unroll
            for (int k = 0; k < 4; k++) acc[i][j][k] = 0.f;

    auto issue = [&](int stage, int k0w) {
        const unsigned ab = sbase + (unsigned)(stage * GSTAGE) * 4u;
        const unsigned bb = ab + (unsigned)(128 * GST) * 4u;
#pragma unroll
        for (int i = 0; i < 2; i++) {
            const int row = crow + i * 64;
            cpa16(ab + (unsigned)(row * GST + cchw) * 4u,
                  Aglob + (size_t)row * (DMODEL / 2) + k0w + cchw);
            cpa16(bb + (unsigned)(row * GST + cchw) * 4u,
                  Bglob + (size_t)row * (DMODEL / 2) + k0w + cchw);
        }
        cpa_commit();
    };

    issue(0, 0);
    issue(1, 16);

    const int NIT = DMODEL / 32;   // 32
    for (int it = 0; it < NIT; it++) {
        const int cur = it % 3;
        if (it == NIT - 1) cpa_wait0(); else cpa_wait1();
        __syncthreads();           // also: all warps done reading stage (it+2)%3

        if (it + 2 < NIT) issue((it + 2) % 3, (it + 2) * 16);

        const unsigned ab = sbase + (unsigned)(cur * GSTAGE) * 4u;
        const unsigned bb = ab + (unsigned)(128 * GST) * 4u;

#pragma unroll
        for (int s = 0; s < 2; s++) {
            const unsigned soff = (unsigned)(s * 8) * 4u;
            unsigned ah[4][4], bf[2][4];
#pragma unroll
            for (int ma = 0; ma < 4; ma++)
                ldsm4(ah[ma], ab + a_off + soff + (unsigned)(ma * 16 * GST) * 4u);
#pragma unroll
            for (int pq = 0; pq < 2; pq++)
                ldsm4(bf[pq], bb + b_off + soff + (unsigned)(pq * 16 * GST) * 4u);
#pragma unroll
            for (int ma = 0; ma < 4; ma++)
#pragma unroll
                for (int na = 0; na < 4; na++)
                    mma16h(acc[ma][na], ah[ma], &bf[na >> 1][(na & 1) * 2]);
        }
    }

    // epilogue
#pragma unroll
    for (int ma = 0; ma < 4; ma++) {
        const int m0 = bm * 128 + wm * 64 + ma * 16 + g;
#pragma unroll
        for (int na = 0; na < 4; na++) {
            const int n  = bn * 128 + wn * 32 + na * 8 + (c << 1);
            const float b0 = bias[n], b1 = bias[n + 1];
            const float v00 = acc[ma][na][0] + b0, v01 = acc[ma][na][1] + b1;
            const float v10 = acc[ma][na][2] + b0, v11 = acc[ma][na][3] + b1;
            if (mode) {
                unsigned* Cp = (unsigned*)Cv + (size_t)z * QKVC;
                const int h = n >> 6, dw = (n & 63) >> 1;
                const int b_0 = m0 >> 11, s_0 = m0 & (S_LEN - 1);
                const int b_1 = (m0 + 8) >> 11, s_1 = (m0 + 8) & (S_LEN - 1);
                Cp[((size_t)((b_0 * NHEAD + h) * S_LEN + s_0)) * 32 + dw] =
                    hpack(scale * v00, scale * v01);
                Cp[((size_t)((b_1 * NHEAD + h) * S_LEN + s_1)) * 32 + dw] =
                    hpack(scale * v10, scale * v11);
            } else {
                float* C = (float*)Cv;
                *(float2*)&C[(size_t)m0 * DMODEL + n]       = make_float2(v00, v01);
                *(float2*)&C[(size_t)(m0 + 8) * DMODEL + n] = make_float2(v10, v11);
            }
        }
    }
}

// ---------------------------------------------------------------------------
// Flash attention, fp16 MMA + ldmatrix, 32 q-rows/warp, register-resident P.
// grid = (16 qtiles of 128 rows, BH). 128 threads = 4 warps.
// smem: Kbuf[2], Vbuf[2] only (36.9 KB).
// ---------------------------------------------------------------------------
#define KW 36
#define KVW (64 * KW)
#define ATTN_SMEM (4 * KVW * 4)

__global__ __launch_bounds__(128) void attn_fp16_kernel(
    const unsigned* __restrict__ Qp, const unsigned* __restrict__ Kp,
    const unsigned* __restrict__ Vt, unsigned* __restrict__ OutP)
{
    extern __shared__ unsigned smem[];

    const int tid  = threadIdx.x;
    const int lane = tid & 31;
    const int w    = tid >> 5;
    const int g    = lane >> 2;
    const int c    = lane & 3;
    const int qtile = blockIdx.x;
    const int bh    = blockIdx.y;

    const unsigned sbase = smem_u32(smem);
    const unsigned kbase[2] = {sbase, sbase + KVW * 4u};
    const unsigned vbase[2] = {sbase + 2u * KVW * 4u, sbase + 3u * KVW * 4u};

    const unsigned off_b =
        ((unsigned)(((lane >> 4) * 8 + (lane & 7)) * KW + ((lane >> 3) & 1) * 4)) * 4u;

    const unsigned* Kt_b = Kp + ((size_t)bh * S_LEN) * 32;
    const unsigned* Vt_b = Vt + (size_t)bh * HDIM * (S_LEN / 2);

    unsigned qa[2][4][4];
    {
        const unsigned* Qw = Qp + ((size_t)bh * S_LEN + qtile * 128 + w * 32) * 32;
#pragma unroll
        for (int mt = 0; mt < 2; mt++)
#pragma unroll
            for (int ks = 0; ks < 4; ks++) {
                qa[mt][ks][0] = Qw[(mt * 16 + g) * 32 + ks * 8 + c];
                qa[mt][ks][1] = Qw[(mt * 16 + g + 8) * 32 + ks * 8 + c];
                qa[mt][ks][2] = Qw[(mt * 16 + g) * 32 + ks * 8 + c + 4];
                qa[mt][ks][3] = Qw[(mt * 16 + g + 8) * 32 + ks * 8 + c + 4];
            }
    }

    float oacc[2][8][4];
#pragma unroll
    for (int mt = 0; mt < 2; mt++)
#pragma unroll
        for (int i = 0; i < 8; i++)
#pragma unroll
            for (int j = 0; j < 4; j++) oacc[mt][i][j] = 0.f;
    float mrow[4] = {-1e30f, -1e30f, -1e30f, -1e30f};
    float lrow[4] = {0.f, 0.f, 0.f, 0.f};

    const int NT = S_LEN / 64;

    {
#pragma unroll
        for (int i = 0; i < 4; i++) {
            const int f = tid + i * 128;
            const int row = f >> 3, ch = f & 7;
            cpa16(kbase[0] + (unsigned)(row * KW + ch * 4) * 4u,
                  Kt_b + (size_t)row * 32 + ch * 4);
            cpa16(vbase[0] + (unsigned)(row * KW + ch * 4) * 4u,
                  Vt_b + (size_t)row * (S_LEN / 2) + ch * 4);
        }
        cpa_commit();
    }

    for (int kt = 0; kt < NT; kt++) {
        const int cur = kt & 1;
        if (kt + 1 < NT) {
            const int nxt = cur ^ 1;
            const unsigned* Ksrc = Kt_b + (size_t)(kt + 1) * 64 * 32;
            const unsigned* Vsrc = Vt_b + (size_t)(kt + 1) * 32;
#pragma unroll
            for (int i = 0; i < 4; i++) {
                const int f = tid + i * 128;
                const int row = f >> 3, ch = f & 7;
                cpa16(kbase[nxt] + (unsigned)(row * KW + ch * 4) * 4u,
                      Ksrc + (size_t)row * 32 + ch * 4);
                cpa16(vbase[nxt] + (unsigned)(row * KW + ch * 4) * 4u,
                      Vsrc + (size_t)row * (S_LEN / 2) + ch * 4);
            }
            cpa_commit();
            cpa_wait1();
        } else {
            cpa_wait0();
        }
        __syncthreads();

        const unsigned ks_b = kbase[cur];
        const unsigned vs_b = vbase[cur];

        // ---- S = (Q/8) @ K^T ----
        float sacc[2][8][4];
#pragma unroll
        for (int mt = 0; mt < 2; mt++)
#pragma unroll
            for (int i = 0; i < 8; i++)
#pragma unroll
                for (int j = 0; j < 4; j++) sacc[mt][i][j] = 0.f;
#pragma unroll
        for (int ks = 0; ks < 4; ks++) {
#pragma unroll
            for (int p = 0; p < 4; p++) {
                unsigned kb[4];
                ldsm4(kb, ks_b + (unsigned)(p * 16 * KW + ks * 8) * 4u + off_b);
#pragma unroll
                for (int mt = 0; mt < 2; mt++) {
                    mma16h(sacc[mt][2 * p],     qa[mt][ks], kb);
                    mma16h(sacc[mt][2 * p + 1], qa[mt][ks], kb + 2);
                }
            }
        }

        // ---- online softmax (P stays in registers) ----
        float tm[4] = {-1e30f, -1e30f, -1e30f, -1e30f};
#pragma unroll
        for (int mt = 0; mt < 2; mt++)
#pragma unroll
            for (int na = 0; na < 8; na++) {
                tm[2 * mt]     = fmaxf(tm[2 * mt],
                                       fmaxf(sacc[mt][na][0], sacc[mt][na][1]));
                tm[2 * mt + 1] = fmaxf(tm[2 * mt + 1],
                                       fmaxf(sacc[mt][na][2], sacc[mt][na][3]));
            }
        float mn[4], alpha[4];
#pragma unroll
        for (int rg = 0; rg < 4; rg++) {
            tm[rg] = fmaxf(tm[rg], __shfl_xor_sync(0xffffffffu, tm[rg], 1));
            tm[rg] = fmaxf(tm[rg], __shfl_xor_sync(0xffffffffu, tm[rg], 2));
            mn[rg] = fmaxf(mrow[rg], tm[rg]);
            alpha[rg] = __expf(mrow[rg] - mn[rg]);
            mrow[rg] = mn[rg];
        }

        float rs[4] = {0.f, 0.f, 0.f, 0.f};
#pragma unroll
        for (int mt = 0; mt < 2; mt++)
#pragma unroll
            for (int na = 0; na < 8; na++) {
                const float p0 = __expf(sacc[mt][na][0] - mn[2 * mt]);
                const float p1 = __expf(sacc[mt][na][1] - mn[2 * mt]);
                const float p2 = __expf(sacc[mt][na][2] - mn[2 * mt + 1]);
                const float p3 = __expf(sacc[mt][na][3] - mn[2 * mt + 1]);
                rs[2 * mt]     += p0 + p1;
                rs[2 * mt + 1] += p2 + p3;
                sacc[mt][na][0] = p0; sacc[mt][na][1] = p1;
                sacc[mt][na][2] = p2; sacc[mt][na][3] = p3;
            }
#pragma unroll
        for (int rg = 0; rg < 4; rg++) {
            rs[rg] += __shfl_xor_sync(0xffffffffu, rs[rg], 1);
            rs[rg] += __shfl_xor_sync(0xffffffffu, rs[rg], 2);
            lrow[rg] = lrow[rg] * alpha[rg] + rs[rg];
        }
#pragma unroll
        for (int mt = 0; mt < 2; mt++)
#pragma unroll
            for (int na = 0; na < 8; na++) {
                oacc[mt][na][0] *= alpha[2 * mt];
                oacc[mt][na][1] *= alpha[2 * mt];
                oacc[mt][na][2] *= alpha[2 * mt + 1];
                oacc[mt][na][3] *= alpha[2 * mt + 1];
            }

        // ---- O += P @ V : P fragments packed directly from registers ----
#pragma unroll
        for (int ks = 0; ks < 4; ks++) {
            unsigned pa[2][4];
#pragma unroll
            for (int mt = 0; mt < 2; mt++) {
                pa[mt][0] = hpack(sacc[mt][2 * ks][0],     sacc[mt][2 * ks][1]);
                pa[mt][1] = hpack(sacc[mt][2 * ks][2],     sacc[mt][2 * ks][3]);
                pa[mt][2] = hpack(sacc[mt][2 * ks + 1][0], sacc[mt][2 * ks + 1][1]);
                pa[mt][3] = hpack(sacc[mt][2 * ks + 1][2], sacc[mt][2 * ks + 1][3]);
            }
#pragma unroll
            for (int p = 0; p < 4; p++) {
                unsigned vb[4];
                ldsm4(vb, vs_b + (unsigned)(p * 16 * KW + ks * 8) * 4u + off_b);
#pragma unroll
                for (int mt = 0; mt < 2; mt++) {
                    mma16h(oacc[mt][2 * p],     pa[mt], vb);
                    mma16h(oacc[mt][2 * p + 1], pa[mt], vb + 2);
                }
            }
        }
        __syncthreads();   // all reads done before next tile's stores
    }

    // ---- epilogue: packed fp16 words for the O projection ----
    const int b = bh >> 4, h = bh & 15;
#pragma unroll
    for (int mt = 0; mt < 2; mt++) {
        const float inv0 = 1.f / lrow[2 * mt];
        const float inv1 = 1.f / lrow[2 * mt + 1];
        const int s0 = qtile * 128 + w * 32 + mt * 16 + g;
        unsigned* o0 = OutP + ((size_t)(b * S_LEN + s0)) * (DMODEL / 2) + h * 32;
        unsigned* o1 = o0 + (size_t)8 * (DMODEL / 2);
#pragma unroll
        for (int na = 0; na < 8; na++) {
            o0[na * 4 + c] = hpack(oacc[mt][na][0] * inv0, oacc[mt][na][1] * inv0);
            o1[na * 4 + c] = hpack(oacc[mt][na][2] * inv1, oacc[mt][na][3] * inv1);
        }
    }
}

// ---------------------------------------------------------------------------
extern "C" void kernel_launch(void* const* d_in, const int* in_sizes, int n_in,
                              void* d_out, int out_size)
{
    const float* query = (const float*)d_in[0];
    const float* key   = (const float*)d_in[1];
    const float* value = (const float*)d_in[2];
    const float* Wq = (const float*)d_in[3];
    const float* bq = (const float*)d_in[4];
    const float* Wk = (const float*)d_in[5];
    const float* bk = (const float*)d_in[6];
    const float* Wv = (const float*)d_in[7];
    const float* bv = (const float*)d_in[8];
    const float* Wo = (const float*)d_in[9];
    const float* bo = (const float*)d_in[10];
    float* out = (float*)d_out;

    unsigned *pIn, *pQKV, *pVt, *pAp, *pWh;
    cudaGetSymbolAddress((void**)&pIn, g_Inp);
    cudaGetSymbolAddress((void**)&pQKV, g_QKVp);
    cudaGetSymbolAddress((void**)&pVt, g_Vt);
    cudaGetSymbolAddress((void**)&pAp, g_attnP);
    cudaGetSymbolAddress((void**)&pWh, g_Wh);

    static int smem_set = 0;
    if (!smem_set) {
        cudaFuncSetAttribute(attn_fp16_kernel,
                             cudaFuncAttributeMaxDynamicSharedMemorySize,
                             ATTN_SMEM);
        cudaFuncSetAttribute(gemm_pk_kernel,
                             cudaFuncAttributeMaxDynamicSharedMemorySize,
                             GEMM_SMEM);
        smem_set = 1;
    }

    dim3 pwgrid(WPK / 256, 4);
    pack_w_kernel<<<pwgrid, 256>>>(Wq, Wk, Wv, Wo, pWh);
    dim3 pigrid(APK / 256, 3);
    pack_in_kernel<<<pigrid, 256>>>(query, key, value, pIn);

    // fused Q/K/V projections: grid.z selects input/weight/bias/output
    dim3 ggrid3(M_ROWS / 128, DMODEL / 128, 3);
    gemm_pk_kernel<<<ggrid3, 256, GEMM_SMEM>>>(
        pIn, pWh, bq, bk, bv, pQKV, 1, 0.125f);

    dim3 vgrid(S_LEN / 64, BH);
    vtrans_kernel<<<vgrid, 256>>>(pQKV + 2 * (size_t)QKVC, pVt);

    dim3 agrid(S_LEN / 128, BH);
    attn_fp16_kernel<<<agrid, 128, ATTN_SMEM>>>(
        pQKV, pQKV + 1 * (size_t)QKVC, pVt, pAp);

    // O projection (z=0 path with scale0=1: plain fp32 output)
    dim3 ggrid1(M_ROWS / 128, DMODEL / 128, 1);
    gemm_pk_kernel<<<ggrid1, 256, GEMM_SMEM>>>(
        pAp, pWh + 3 * (size_t)WPK, bo, bo, bo, out, 0, 1.0f);
}

// round 14
// speedup vs baseline: 2.4901x; 1.0268x over previous
#include <cuda_runtime.h>
#include <cuda_fp16.h>

#define S_LEN   2048
#define DMODEL  1024
#define NHEAD   16
#define HDIM    64
#define BATCH   2
#define M_ROWS  (BATCH * S_LEN)   /* 4096 */
#define BH      (BATCH * NHEAD)   /* 32 */

// Scratch (allocation-free rule: __device__ globals).
// NOTE: APK (input rows = 4096) != WPK (weight rows = 1024). Round-12 bug.
#define APK (M_ROWS * (DMODEL / 2))          /* 2,097,152 words */
#define WPK (DMODEL * (DMODEL / 2))          /*   524,288 words */
#define QKVC (BH * S_LEN * (HDIM / 2))       /* == APK */
__device__ unsigned g_Inp[3 * APK];          /* packed query/key/value */
__device__ unsigned g_QKVp[3 * QKVC];        /* packed Q,K,V headsplit */
__device__ unsigned g_Vt[BH * HDIM * (S_LEN / 2)];
__device__ unsigned g_attnP[M_ROWS * (DMODEL / 2)];
__device__ unsigned g_Wh[4 * WPK];

// ---------------------------------------------------------------------------
// helpers
// ---------------------------------------------------------------------------
__device__ __forceinline__ void mma16h(float* d, const unsigned* a, const unsigned* b) {
    asm volatile(
        "mma.sync.aligned.m16n8k16.row.col.f32.f16.f16.f32 "
        "{%0,%1,%2,%3}, {%4,%5,%6,%7}, {%8,%9}, {%0,%1,%2,%3};\n"
        : "+f"(d[0]), "+f"(d[1]), "+f"(d[2]), "+f"(d[3])
        : "r"(a[0]), "r"(a[1]), "r"(a[2]), "r"(a[3]), "r"(b[0]), "r"(b[1]));
}

__device__ __forceinline__ void ldsm4(unsigned* r, unsigned addr) {
    asm volatile(
        "ldmatrix.sync.aligned.m8n8.x4.shared.b16 {%0,%1,%2,%3}, [%4];"
        : "=r"(r[0]), "=r"(r[1]), "=r"(r[2]), "=r"(r[3]) : "r"(addr));
}

__device__ __forceinline__ unsigned hpack(float lo_k, float hi_k) {
    __half2 t = __floats2half2_rn(lo_k, hi_k);             // .x = even k (low)
    return *(unsigned*)&t;
}

__device__ __forceinline__ unsigned smem_u32(const void* p) {
    return (unsigned)__cvta_generic_to_shared(p);
}

__device__ __forceinline__ void cpa16(unsigned dst, const void* src) {
    asm volatile("cp.async.cg.shared.global [%0], [%1], 16;\n"
                 :: "r"(dst), "l"(src));
}
__device__ __forceinline__ void cpa_commit() {
    asm volatile("cp.async.commit_group;\n");
}
__device__ __forceinline__ void cpa_wait1() {
    asm volatile("cp.async.wait_group 1;\n");
}
__device__ __forceinline__ void cpa_wait0() {
    asm volatile("cp.async.wait_group 0;\n");
}

// ---------------------------------------------------------------------------
// packers (separate launches — grids sized per tensor; round-12 bug fixed)
// ---------------------------------------------------------------------------
__global__ __launch_bounds__(256) void pack_w_kernel(
    const float* __restrict__ W0, const float* __restrict__ W1,
    const float* __restrict__ W2, const float* __restrict__ W3,
    unsigned* __restrict__ Wh)
{
    const int by = blockIdx.y;
    const float* W = (by == 0) ? W0 : (by == 1) ? W1 : (by == 2) ? W2 : W3;
    const size_t i = (size_t)blockIdx.x * 256 + threadIdx.x;   // < WPK
    float2 v = *(const float2*)(W + i * 2);
    Wh[(size_t)by * WPK + i] = hpack(v.x, v.y);
}

__global__ __launch_bounds__(256) void pack_in_kernel(
    const float* __restrict__ q, const float* __restrict__ k,
    const float* __restrict__ v, unsigned* __restrict__ dst)
{
    const int by = blockIdx.y;
    const float* src = (by == 0) ? q : (by == 1) ? k : v;
    const size_t i = (size_t)blockIdx.x * 256 + threadIdx.x;   // < APK
    float2 val = *(const float2*)(src + i * 2);
    dst[(size_t)by * APK + i] = hpack(val.x, val.y);
}

// ---------------------------------------------------------------------------
// V transpose-pack: Vp [bh][key][32 d-words] -> Vt [bh][d][key-pair words]
// ---------------------------------------------------------------------------
__global__ __launch_bounds__(256) void vtrans_kernel(
    const unsigned* __restrict__ Vp, unsigned* __restrict__ Vt)
{
    __shared__ unsigned sT[64 * 33];
    const int t  = threadIdx.x;
    const int kt = blockIdx.x;
    const int bh = blockIdx.y;

    const unsigned* src = Vp + ((size_t)bh * S_LEN + kt * 64) * (HDIM / 2);
#pragma unroll
    for (int i = 0; i < 8; i++) {
        const int idx = t + i * 256;
        sT[(idx >> 5) * 33 + (idx & 31)] = src[idx];
    }
    __syncthreads();

    unsigned* dst = Vt + (size_t)bh * HDIM * (S_LEN / 2) + kt * 32;
#pragma unroll
    for (int i = 0; i < 8; i++) {
        const int idx = t + i * 256;
        const int kp = idx & 31;
        const int d  = idx >> 5;
        const unsigned w0 = sT[(2 * kp) * 33 + (d >> 1)];
        const unsigned w1 = sT[(2 * kp + 1) * 33 + (d >> 1)];
        dst[(size_t)d * (S_LEN / 2) + kp] =
            __byte_perm(w0, w1, (d & 1) ? 0x7632 : 0x5410);
    }
}

// ---------------------------------------------------------------------------
// Pipelined fp16 GEMM, ldmatrix fragments, BK=64, 3-stage cp.async ring.
// CTA 128x128, 256 threads (8 warps, 2Mx4N). 16 iters, 1 sync each.
// blockIdx.z selects input/weight/bias/output (fused QKV projections).
// mode 1: headsplit packed fp16 out (*scale for z==0); mode 0: flat fp32.
// ---------------------------------------------------------------------------
#define GST 36   /* row stride words: 32 data + 4 pad (ldsm conflict-free) */
#define GSTAGE (2 * 128 * GST)            /* words per stage (A then B) */
#define GEMM_SMEM (3 * GSTAGE * 4)        /* 110592 bytes */

__global__ __launch_bounds__(256) void gemm_pk_kernel(
    const unsigned* __restrict__ Abase, const unsigned* __restrict__ Wbase,
    const float* __restrict__ b0p, const float* __restrict__ b1p,
    const float* __restrict__ b2p, void* __restrict__ Cv,
    int mode, float scale0)
{
    extern __shared__ unsigned gs[];

    const int tid  = threadIdx.x;
    const int lane = tid & 31;
    const int wid  = tid >> 5;
    const int wm   = wid >> 2;
    const int wn   = wid & 3;
    const int g    = lane >> 2;
    const int c    = lane & 3;
    const int bm   = blockIdx.x;
    const int bn   = blockIdx.y;
    const int z    = blockIdx.z;

    const float* bias = (z == 0) ? b0p : (z == 1) ? b1p : b2p;
    const float scale = (z == 0) ? scale0 : 1.0f;

    const unsigned sbase = smem_u32(gs);

    const unsigned* Aglob = Abase + (size_t)z * APK + (size_t)(bm * 128) * (DMODEL / 2);
    const unsigned* Bglob = Wbase + (size_t)z * WPK + (size_t)(bn * 128) * (DMODEL / 2);

    // ldmatrix lane offsets (bytes)
    const unsigned a_off =
        ((unsigned)((wm * 64 + ((lane >> 3) & 1) * 8 + (lane & 7)) * GST
                    + (lane >> 4) * 4)) * 4u;
    const unsigned b_off =
        ((unsigned)((wn * 32 + (lane >> 4) * 8 + (lane & 7)) * GST
                    + ((lane >> 3) & 1) * 4)) * 4u;

    float acc[4][4][4];
#pragma unroll
    for (int i = 0; i < 4; i++)
#pragma unroll
        for (int j = 0; j < 4; j++)
#pragma unroll
            for (int k = 0; k < 4; k++) acc[i][j][k] = 0.f;

    // issue one 64-k stage: A 1024 chunks + B 1024 chunks, 8 per thread
    auto issue = [&](int stage, int k0w) {
        const unsigned ab = sbase + (unsigned)(stage * GSTAGE) * 4u;
        const unsigned bb = ab + (unsigned)(128 * GST) * 4u;
#pragma unroll
        for (int i = 0; i < 4; i++) {
            const int id  = tid + i * 256;          // 0..1023
            const int row = id >> 3;
            const int chw = (id & 7) * 4;
            cpa16(ab + (unsigned)(row * GST + chw) * 4u,
                  Aglob + (size_t)row * (DMODEL / 2) + k0w + chw);
            cpa16(bb + (unsigned)(row * GST + chw) * 4u,
                  Bglob + (size_t)row * (DMODEL / 2) + k0w + chw);
        }
        cpa_commit();
    };

    issue(0, 0);
    issue(1, 32);

    const int NIT = DMODEL / 64;   // 16
    for (int it = 0; it < NIT; it++) {
        const int cur = it % 3;
        if (it == NIT - 1) cpa_wait0(); else cpa_wait1();
        __syncthreads();           // also: all warps done reading stage (it+2)%3

        if (it + 2 < NIT) issue((it + 2) % 3, (it + 2) * 32);

        const unsigned ab = sbase + (unsigned)(cur * GSTAGE) * 4u;
        const unsigned bb = ab + (unsigned)(128 * GST) * 4u;

#pragma unroll
        for (int s = 0; s < 4; s++) {
            const unsigned soff = (unsigned)(s * 8) * 4u;
            unsigned ah[4][4], bf[2][4];
#pragma unroll
            for (int ma = 0; ma < 4; ma++)
                ldsm4(ah[ma], ab + a_off + soff + (unsigned)(ma * 16 * GST) * 4u);
#pragma unroll
            for (int pq = 0; pq < 2; pq++)
                ldsm4(bf[pq], bb + b_off + soff + (unsigned)(pq * 16 * GST) * 4u);
#pragma unroll
            for (int ma = 0; ma < 4; ma++)
#pragma unroll
                for (int na = 0; na < 4; na++)
                    mma16h(acc[ma][na], ah[ma], &bf[na >> 1][(na & 1) * 2]);
        }
    }

    // epilogue
#pragma unroll
    for (int ma = 0; ma < 4; ma++) {
        const int m0 = bm * 128 + wm * 64 + ma * 16 + g;
#pragma unroll
        for (int na = 0; na < 4; na++) {
            const int n  = bn * 128 + wn * 32 + na * 8 + (c << 1);
            const float b0 = bias[n], b1 = bias[n + 1];
            const float v00 = acc[ma][na][0] + b0, v01 = acc[ma][na][1] + b1;
            const float v10 = acc[ma][na][2] + b0, v11 = acc[ma][na][3] + b1;
            if (mode) {
                unsigned* Cp = (unsigned*)Cv + (size_t)z * QKVC;
                const int h = n >> 6, dw = (n & 63) >> 1;
                const int b_0 = m0 >> 11, s_0 = m0 & (S_LEN - 1);
                const int b_1 = (m0 + 8) >> 11, s_1 = (m0 + 8) & (S_LEN - 1);
                Cp[((size_t)((b_0 * NHEAD + h) * S_LEN + s_0)) * 32 + dw] =
                    hpack(scale * v00, scale * v01);
                Cp[((size_t)((b_1 * NHEAD + h) * S_LEN + s_1)) * 32 + dw] =
                    hpack(scale * v10, scale * v11);
            } else {
                float* C = (float*)Cv;
                *(float2*)&C[(size_t)m0 * DMODEL + n]       = make_float2(v00, v01);
                *(float2*)&C[(size_t)(m0 + 8) * DMODEL + n] = make_float2(v10, v11);
            }
        }
    }
}

// ---------------------------------------------------------------------------
// Flash attention, fp16 MMA + ldmatrix, register-resident P,
// 8 warps x 32 q-rows = 256 q-rows per CTA. grid = (8, BH) = 256 CTAs.
// smem: Kbuf[2], Vbuf[2] (36.9 KB).
// ---------------------------------------------------------------------------
#define KW 36
#define KVW (64 * KW)
#define ATTN_SMEM (4 * KVW * 4)

__global__ __launch_bounds__(256) void attn_fp16_kernel(
    const unsigned* __restrict__ Qp, const unsigned* __restrict__ Kp,
    const unsigned* __restrict__ Vt, unsigned* __restrict__ OutP)
{
    extern __shared__ unsigned smem[];

    const int tid  = threadIdx.x;
    const int lane = tid & 31;
    const int w    = tid >> 5;            // 0..7
    const int g    = lane >> 2;
    const int c    = lane & 3;
    const int qtile = blockIdx.x;         // 0..7 (256 q-rows each)
    const int bh    = blockIdx.y;

    const unsigned sbase = smem_u32(smem);
    const unsigned kbase[2] = {sbase, sbase + KVW * 4u};
    const unsigned vbase[2] = {sbase + 2u * KVW * 4u, sbase + 3u * KVW * 4u};

    const unsigned off_b =
        ((unsigned)(((lane >> 4) * 8 + (lane & 7)) * KW + ((lane >> 3) & 1) * 4)) * 4u;

    const unsigned* Kt_b = Kp + ((size_t)bh * S_LEN) * 32;
    const unsigned* Vt_b = Vt + (size_t)bh * HDIM * (S_LEN / 2);

    unsigned qa[2][4][4];
    {
        const unsigned* Qw = Qp + ((size_t)bh * S_LEN + qtile * 256 + w * 32) * 32;
#pragma unroll
        for (int mt = 0; mt < 2; mt++)
#pragma unroll
            for (int ks = 0; ks < 4; ks++) {
                qa[mt][ks][0] = Qw[(mt * 16 + g) * 32 + ks * 8 + c];
                qa[mt][ks][1] = Qw[(mt * 16 + g + 8) * 32 + ks * 8 + c];
                qa[mt][ks][2] = Qw[(mt * 16 + g) * 32 + ks * 8 + c + 4];
                qa[mt][ks][3] = Qw[(mt * 16 + g + 8) * 32 + ks * 8 + c + 4];
            }
    }

    float oacc[2][8][4];
#pragma unroll
    for (int mt = 0; mt < 2; mt++)
#pragma unroll
        for (int i = 0; i < 8; i++)
#pragma unroll
            for (int j = 0; j < 4; j++) oacc[mt][i][j] = 0.f;
    float mrow[4] = {-1e30f, -1e30f, -1e30f, -1e30f};
    float lrow[4] = {0.f, 0.f, 0.f, 0.f};

    const int NT = S_LEN / 64;

    // prologue: tile 0 into buffer 0 (512 K-chunks + 512 V-chunks)
    {
#pragma unroll
        for (int i = 0; i < 2; i++) {
            const int f = tid + i * 256;           // 0..511
            const int row = f >> 3, ch = f & 7;
            cpa16(kbase[0] + (unsigned)(row * KW + ch * 4) * 4u,
                  Kt_b + (size_t)row * 32 + ch * 4);
            cpa16(vbase[0] + (unsigned)(row * KW + ch * 4) * 4u,
                  Vt_b + (size_t)row * (S_LEN / 2) + ch * 4);
        }
        cpa_commit();
    }

    for (int kt = 0; kt < NT; kt++) {
        const int cur = kt & 1;
        if (kt + 1 < NT) {
            const int nxt = cur ^ 1;
            const unsigned* Ksrc = Kt_b + (size_t)(kt + 1) * 64 * 32;
            const unsigned* Vsrc = Vt_b + (size_t)(kt + 1) * 32;
#pragma unroll
            for (int i = 0; i < 2; i++) {
                const int f = tid + i * 256;
                const int row = f >> 3, ch = f & 7;
                cpa16(kbase[nxt] + (unsigned)(row * KW + ch * 4) * 4u,
                      Ksrc + (size_t)row * 32 + ch * 4);
                cpa16(vbase[nxt] + (unsigned)(row * KW + ch * 4) * 4u,
                      Vsrc + (size_t)row * (S_LEN / 2) + ch * 4);
            }
            cpa_commit();
            cpa_wait1();
        } else {
            cpa_wait0();
        }
        __syncthreads();

        const unsigned ks_b = kbase[cur];
        const unsigned vs_b = vbase[cur];

        // ---- S = (Q/8) @ K^T ----
        float sacc[2][8][4];
#pragma unroll
        for (int mt = 0; mt < 2; mt++)
#pragma unroll
            for (int i = 0; i < 8; i++)
#pragma unroll
                for (int j = 0; j < 4; j++) sacc[mt][i][j] = 0.f;
#pragma unroll
        for (int ks = 0; ks < 4; ks++) {
#pragma unroll
            for (int p = 0; p < 4; p++) {
                unsigned kb[4];
                ldsm4(kb, ks_b + (unsigned)(p * 16 * KW + ks * 8) * 4u + off_b);
#pragma unroll
                for (int mt = 0; mt < 2; mt++) {
                    mma16h(sacc[mt][2 * p],     qa[mt][ks], kb);
                    mma16h(sacc[mt][2 * p + 1], qa[mt][ks], kb + 2);
                }
            }
        }

        // ---- online softmax (P stays in registers) ----
        float tm[4] = {-1e30f, -1e30f, -1e30f, -1e30f};
#pragma unroll
        for (int mt = 0; mt < 2; mt++)
#pragma unroll
            for (int na = 0; na < 8; na++) {
                tm[2 * mt]     = fmaxf(tm[2 * mt],
                                       fmaxf(sacc[mt][na][0], sacc[mt][na][1]));
                tm[2 * mt + 1] = fmaxf(tm[2 * mt + 1],
                                       fmaxf(sacc[mt][na][2], sacc[mt][na][3]));
            }
        float mn[4], alpha[4];
#pragma unroll
        for (int rg = 0; rg < 4; rg++) {
            tm[rg] = fmaxf(tm[rg], __shfl_xor_sync(0xffffffffu, tm[rg], 1));
            tm[rg] = fmaxf(tm[rg], __shfl_xor_sync(0xffffffffu, tm[rg], 2));
            mn[rg] = fmaxf(mrow[rg], tm[rg]);
            alpha[rg] = __expf(mrow[rg] - mn[rg]);
            mrow[rg] = mn[rg];
        }

        float rs[4] = {0.f, 0.f, 0.f, 0.f};
#pragma unroll
        for (int mt = 0; mt < 2; mt++)
#pragma unroll
            for (int na = 0; na < 8; na++) {
                const float p0 = __expf(sacc[mt][na][0] - mn[2 * mt]);
                const float p1 = __expf(sacc[mt][na][1] - mn[2 * mt]);
                const float p2 = __expf(sacc[mt][na][2] - mn[2 * mt + 1]);
                const float p3 = __expf(sacc[mt][na][3] - mn[2 * mt + 1]);
                rs[2 * mt]     += p0 + p1;
                rs[2 * mt + 1] += p2 + p3;
                sacc[mt][na][0] = p0; sacc[mt][na][1] = p1;
                sacc[mt][na][2] = p2; sacc[mt][na][3] = p3;
            }
#pragma unroll
        for (int rg = 0; rg < 4; rg++) {
            rs[rg] += __shfl_xor_sync(0xffffffffu, rs[rg], 1);
            rs[rg] += __shfl_xor_sync(0xffffffffu, rs[rg], 2);
            lrow[rg] = lrow[rg] * alpha[rg] + rs[rg];
        }
#pragma unroll
        for (int mt = 0; mt < 2; mt++)
#pragma unroll
            for (int na = 0; na < 8; na++) {
                oacc[mt][na][0] *= alpha[2 * mt];
                oacc[mt][na][1] *= alpha[2 * mt];
                oacc[mt][na][2] *= alpha[2 * mt + 1];
                oacc[mt][na][3] *= alpha[2 * mt + 1];
            }

        // ---- O += P @ V : P fragments packed directly from registers ----
#pragma unroll
        for (int ks = 0; ks < 4; ks++) {
            unsigned pa[2][4];
#pragma unroll
            for (int mt = 0; mt < 2; mt++) {
                pa[mt][0] = hpack(sacc[mt][2 * ks][0],     sacc[mt][2 * ks][1]);
                pa[mt][1] = hpack(sacc[mt][2 * ks][2],     sacc[mt][2 * ks][3]);
                pa[mt][2] = hpack(sacc[mt][2 * ks + 1][0], sacc[mt][2 * ks + 1][1]);
                pa[mt][3] = hpack(sacc[mt][2 * ks + 1][2], sacc[mt][2 * ks + 1][3]);
            }
#pragma unroll
            for (int p = 0; p < 4; p++) {
                unsigned vb[4];
                ldsm4(vb, vs_b + (unsigned)(p * 16 * KW + ks * 8) * 4u + off_b);
#pragma unroll
                for (int mt = 0; mt < 2; mt++) {
                    mma16h(oacc[mt][2 * p],     pa[mt], vb);
                    mma16h(oacc[mt][2 * p + 1], pa[mt], vb + 2);
                }
            }
        }
        __syncthreads();   // all reads done before next tile's stores
    }

    // ---- epilogue: packed fp16 words for the O projection ----
    const int b = bh >> 4, h = bh & 15;
#pragma unroll
    for (int mt = 0; mt < 2; mt++) {
        const float inv0 = 1.f / lrow[2 * mt];
        const float inv1 = 1.f / lrow[2 * mt + 1];
        const int s0 = qtile * 256 + w * 32 + mt * 16 + g;
        unsigned* o0 = OutP + ((size_t)(b * S_LEN + s0)) * (DMODEL / 2) + h * 32;
        unsigned* o1 = o0 + (size_t)8 * (DMODEL / 2);
#pragma unroll
        for (int na = 0; na < 8; na++) {
            o0[na * 4 + c] = hpack(oacc[mt][na][0] * inv0, oacc[mt][na][1] * inv0);
            o1[na * 4 + c] = hpack(oacc[mt][na][2] * inv1, oacc[mt][na][3] * inv1);
        }
    }
}

// ---------------------------------------------------------------------------
extern "C" void kernel_launch(void* const* d_in, const int* in_sizes, int n_in,
                              void* d_out, int out_size)
{
    const float* query = (const float*)d_in[0];
    const float* key   = (const float*)d_in[1];
    const float* value = (const float*)d_in[2];
    const float* Wq = (const float*)d_in[3];
    const float* bq = (const float*)d_in[4];
    const float* Wk = (const float*)d_in[5];
    const float* bk = (const float*)d_in[6];
    const float* Wv = (const float*)d_in[7];
    const float* bv = (const float*)d_in[8];
    const float* Wo = (const float*)d_in[9];
    const float* bo = (const float*)d_in[10];
    float* out = (float*)d_out;

    unsigned *pIn, *pQKV, *pVt, *pAp, *pWh;
    cudaGetSymbolAddress((void**)&pIn, g_Inp);
    cudaGetSymbolAddress((void**)&pQKV, g_QKVp);
    cudaGetSymbolAddress((void**)&pVt, g_Vt);
    cudaGetSymbolAddress((void**)&pAp, g_attnP);
    cudaGetSymbolAddress((void**)&pWh, g_Wh);

    static int smem_set = 0;
    if (!smem_set) {
        cudaFuncSetAttribute(attn_fp16_kernel,
                             cudaFuncAttributeMaxDynamicSharedMemorySize,
                             ATTN_SMEM);
        cudaFuncSetAttribute(gemm_pk_kernel,
                             cudaFuncAttributeMaxDynamicSharedMemorySize,
                             GEMM_SMEM);
        smem_set = 1;
    }

    // pack weights (WPK-sized grid) and inputs (APK-sized grid) separately
    dim3 pwgrid(WPK / 256, 4);
    pack_w_kernel<<<pwgrid, 256>>>(Wq, Wk, Wv, Wo, pWh);
    dim3 pigrid(APK / 256, 3);
    pack_in_kernel<<<pigrid, 256>>>(query, key, value, pIn);

    // fused Q/K/V projections: grid.z selects input/weight/bias/output
    dim3 ggrid3(M_ROWS / 128, DMODEL / 128, 3);
    gemm_pk_kernel<<<ggrid3, 256, GEMM_SMEM>>>(
        pIn, pWh, bq, bk, bv, pQKV, 1, 0.125f);

    dim3 vgrid(S_LEN / 64, BH);
    vtrans_kernel<<<vgrid, 256>>>(pQKV + 2 * (size_t)QKVC, pVt);

    dim3 agrid(S_LEN / 256, BH);
    attn_fp16_kernel<<<agrid, 256, ATTN_SMEM>>>(
        pQKV, pQKV + 1 * (size_t)QKVC, pVt, pAp);

    // O projection (z=0 path; mode 0: plain fp32 output)
    dim3 ggrid1(M_ROWS / 128, DMODEL / 128, 1);
    gemm_pk_kernel<<<ggrid1, 256, GEMM_SMEM>>>(
        pAp, pWh + 3 * (size_t)WPK, bo, bo, bo, out, 0, 1.0f);
}